// round 12
// baseline (speedup 1.0000x reference)
#include <cuda_runtime.h>
#include <cuda_fp16.h>
#include <cstdint>
#include <math.h>

// ---------------- scratch (static device globals; no allocation) ----------
__device__ float g_Q[4096 * 2048];
__device__ float g_K[4096 * 2048];
__device__ float g_V[4096 * 2048];
__device__ __half g_Xh[4096 * 2048];     // x fp16; later attention-out fp16
__device__ __half g_Wh[2048 * 2048];     // weight fp16
__device__ __half g_Qh[4096 * 2048];
__device__ __half g_Kh[4096 * 2048];
__device__ __half g_VTh[2048 * 4096];    // [h*128+d][s], fp16

// ======================= portable PTX helpers (sm_80+) =====================
__device__ __forceinline__ uint32_t smem_u32(const void* p) {
    uint32_t a;
    asm("{ .reg .u64 t; cvta.to.shared.u64 t, %1; cvt.u32.u64 %0, t; }"
        : "=r"(a) : "l"(p));
    return a;
}
#define CP_ASYNC16(dst, src) \
    asm volatile("cp.async.cg.shared.global [%0], [%1], 16;" \
                 :: "r"(dst), "l"(src))
#define CP_COMMIT() asm volatile("cp.async.commit_group;")
#define CP_WAIT1()  asm volatile("cp.async.wait_group 1;")
#define CP_WAIT0()  asm volatile("cp.async.wait_group 0;")
#define LDSM_X4(r, addr) \
    asm volatile("ldmatrix.sync.aligned.m8n8.x4.shared.b16 {%0,%1,%2,%3}, [%4];" \
                 : "=r"((r)[0]), "=r"((r)[1]), "=r"((r)[2]), "=r"((r)[3]) \
                 : "r"(addr))
#define MMAF16(d, a, b0, b1) \
    asm volatile("mma.sync.aligned.m16n8k16.row.col.f32.f16.f16.f32 " \
                 "{%0,%1,%2,%3}, {%4,%5,%6,%7}, {%8,%9}, {%0,%1,%2,%3};" \
                 : "+f"((d)[0]), "+f"((d)[1]), "+f"((d)[2]), "+f"((d)[3]) \
                 : "r"((a)[0]), "r"((a)[1]), "r"((a)[2]), "r"((a)[3]), \
                   "r"(b0), "r"(b1))
__device__ __forceinline__ float ex2(float x) {
    float r;
    asm("ex2.approx.f32 %0, %1;" : "=f"(r) : "f"(x));
    return r;
}

// ---------------------------------------------------------------------------
// convert fp32 -> fp16
// ---------------------------------------------------------------------------
__global__ void __launch_bounds__(256) conv_h(const float* __restrict__ in,
                                              __half* __restrict__ out, int n4) {
    int i = blockIdx.x * blockDim.x + threadIdx.x;
    if (i >= n4) return;
    float4 v = ((const float4*)in)[i];
    union { __half b[4]; uint2 u; } H;
    H.b[0] = __float2half_rn(v.x);
    H.b[1] = __float2half_rn(v.y);
    H.b[2] = __float2half_rn(v.z);
    H.b[3] = __float2half_rn(v.w);
    ((uint2*)out)[i] = H.u;
}

// ---------------------------------------------------------------------------
// fused rmsnorm + scale + fp16 convert (one warp / (token,head) row)
// ---------------------------------------------------------------------------
__global__ void __launch_bounds__(256) rmsnorm_h(
    const float* __restrict__ X, const float* __restrict__ w,
    __half* __restrict__ out, int nrows, float scale) {
    int warp = (blockIdx.x * blockDim.x + threadIdx.x) >> 5;
    int lane = threadIdx.x & 31;
    if (warp >= nrows) return;

    float4 v = *(const float4*)&X[(size_t)warp * 128 + (lane << 2)];
    float ss = v.x * v.x + v.y * v.y + v.z * v.z + v.w * v.w;
#pragma unroll
    for (int off = 16; off > 0; off >>= 1)
        ss += __shfl_xor_sync(0xffffffffu, ss, off);

    float inv = rsqrtf(ss * (1.0f / 128.0f) + 1e-6f) * scale;
    float4 wv = *(const float4*)&w[lane << 2];
    union { __half b[4]; uint2 u; } H;
    H.b[0] = __float2half_rn(v.x * inv * wv.x);
    H.b[1] = __float2half_rn(v.y * inv * wv.y);
    H.b[2] = __float2half_rn(v.z * inv * wv.z);
    H.b[3] = __float2half_rn(v.w * inv * wv.w);
    ((uint2*)out)[(size_t)warp * 32 + lane] = H.u;
}

// ---------------------------------------------------------------------------
// transpose + fp16 convert V: [4096][2048] fp32 -> VT [2048][4096] fp16
// ---------------------------------------------------------------------------
__global__ void __launch_bounds__(256) transpose_h(
    const float* __restrict__ in, __half* __restrict__ th) {
    __shared__ float t[32][33];
    const int s0 = blockIdx.x << 5;
    const int c0 = blockIdx.y << 5;
    const int tx = threadIdx.x & 31;
    const int ty = threadIdx.x >> 5;
#pragma unroll
    for (int i = 0; i < 4; i++) {
        int r = (ty << 2) + i;
        t[r][tx] = in[(size_t)(s0 + r) * 2048 + c0 + tx];
    }
    __syncthreads();
#pragma unroll
    for (int i = 0; i < 4; i++) {
        int r = (ty << 2) + i;
        th[(size_t)(c0 + r) * 4096 + s0 + tx] = __float2half_rn(t[tx][r]);
    }
}

// ---------------------------------------------------------------------------
// gemm fp16 v4:  C = Ah * Bh^T, CTA tile 256x128 (fewer bytes/MMA: 46 vs 61),
// 8 warps (warp tile 64x64), K chunk 32 (64B rows), 3-stage cp.async,
// 1 sync/iter, NITER=64, 1 CTA/SM. Stage = A 16KB | B 8KB.
// ---------------------------------------------------------------------------
#define GMS      24576              // stage: A(16KB) + B(8KB)
#define GM_SMEM  (3 * GMS)          // 73728

__global__ void __launch_bounds__(256, 1) gemm_mma(
    const __half* __restrict__ Ah, const __half* __restrict__ Bh,
    float* __restrict__ C) {
    constexpr int Nd = 2048, Kd = 2048;
    extern __shared__ char smem[];
    const uint32_t sbase = smem_u32(smem);
    const int tid = threadIdx.x;
    const int lane = tid & 31;
    const int wid = tid >> 5;
    const int m0 = blockIdx.y << 8;      // 256-row tile
    const int n0 = blockIdx.x << 7;      // 128-col tile
    const int wm = (wid & 3) << 6;       // 0/64/128/192
    const int wn = (wid >> 2) << 6;      // 0/64

    float acc[4][8][4];
#pragma unroll
    for (int mi = 0; mi < 4; mi++)
#pragma unroll
        for (int ni = 0; ni < 8; ni++)
#pragma unroll
            for (int q = 0; q < 4; q++) acc[mi][ni][q] = 0.f;

    // loader: A rows 0..255 (1 row/thread, 4 chunks), B rows 0..127 (2 thr/row)
    const int brow = tid >> 1;
    const int bc0 = (tid & 1) << 1;

    auto issue = [&](int it, int stage) {
        int kk = it << 5;
        const __half* pA = Ah + (size_t)(m0 + tid) * Kd + kk;
        uint32_t stA = sbase + stage * GMS + tid * 64;
#pragma unroll
        for (int c = 0; c < 4; c++) {
            uint32_t sw = (uint32_t)((c ^ ((tid >> 1) & 3)) << 4);
            CP_ASYNC16(stA + sw, pA + c * 8);
        }
        const __half* pB = Bh + (size_t)(n0 + brow) * Kd + kk;
        uint32_t stB = sbase + stage * GMS + 16384 + brow * 64;
#pragma unroll
        for (int j = 0; j < 2; j++) {
            int c = bc0 + j;
            uint32_t sw = (uint32_t)((c ^ ((brow >> 1) & 3)) << 4);
            CP_ASYNC16(stB + sw, pB + c * 8);
        }
    };

    issue(0, 0); CP_COMMIT();
    issue(1, 1); CP_COMMIT();

    constexpr int NITER = 64;            // 2048 / 32
    int stage = 0, nstage = 2;
    for (int it = 0; it < NITER; it++) {
        if (it < NITER - 1) CP_WAIT1(); else CP_WAIT0();
        __syncthreads();
        if (it + 2 < NITER) { issue(it + 2, nstage); CP_COMMIT(); }

        const uint32_t sA = sbase + stage * GMS;
        const uint32_t sB = sA + 16384;

#pragma unroll
        for (int ks = 0; ks < 2; ks++) {
            uint32_t bh[4][4];
#pragma unroll
            for (int pr = 0; pr < 4; pr++) {
                int row = wn + pr * 16 + (lane & 7) + (((lane >> 4) & 1) << 3);
                int c = ks * 2 + ((lane >> 3) & 1);
                uint32_t off = (uint32_t)(row * 64 + ((c ^ ((row >> 1) & 3)) << 4));
                LDSM_X4(bh[pr], sB + off);
            }
#pragma unroll
            for (int mi = 0; mi < 4; mi++) {
                uint32_t ah[4];
                int row = wm + mi * 16 + (lane & 15);
                int c = ks * 2 + (lane >> 4);
                uint32_t off = (uint32_t)(row * 64 + ((c ^ ((row >> 1) & 3)) << 4));
                LDSM_X4(ah, sA + off);
#pragma unroll
                for (int ni = 0; ni < 8; ni++)
                    MMAF16(acc[mi][ni], ah,
                           bh[ni >> 1][(ni & 1) << 1],
                           bh[ni >> 1][((ni & 1) << 1) + 1]);
            }
        }
        stage = (stage == 2) ? 0 : stage + 1;
        nstage = (nstage == 2) ? 0 : nstage + 1;
    }

    // epilogue
#pragma unroll
    for (int mi = 0; mi < 4; mi++) {
        int r0 = m0 + wm + mi * 16 + (lane >> 2);
#pragma unroll
        for (int ni = 0; ni < 8; ni++) {
            int cc = n0 + wn + ni * 8 + ((lane & 3) << 1);
            *(float2*)&C[(size_t)r0 * Nd + cc] =
                make_float2(acc[mi][ni][0], acc[mi][ni][1]);
            *(float2*)&C[(size_t)(r0 + 8) * Nd + cc] =
                make_float2(acc[mi][ni][2], acc[mi][ni][3]);
        }
    }
}

// ---------------------------------------------------------------------------
// Flash attention fp16 1-pass (unchanged from round 11).
// ---------------------------------------------------------------------------
#define FM_QH    0
#define FM_STG0  32768
#define FM_STAGE 32768               // Kh 16KB | Vh 16KB
#define FM_SMEM  (32768 + 2 * FM_STAGE)   // 98304

__device__ __forceinline__ uint32_t sw256(int row, int kb) {
    return (uint32_t)(row * 256 + ((kb & 0x80) | ((kb ^ ((row & 7) << 4)) & 0x70)));
}

__global__ void __launch_bounds__(256, 1) flash_mma(
    const __half* __restrict__ Qh, const __half* __restrict__ Kh,
    const __half* __restrict__ VTh, __half* __restrict__ Oh) {
    extern __shared__ char smem[];
    const uint32_t sb = smem_u32(smem);
    const int tid = threadIdx.x;
    const int lane = tid & 31;
    const int wid = tid >> 5;
    const int h = blockIdx.y;
    const int m0 = blockIdx.x << 7;
    const int hoff = h << 7;
    const int qbase = wid << 4;

    // ---- load Q tile ----
    {
        int row = tid >> 1;
        int c0 = (tid & 1) << 3;
        const __half* qh = Qh + (size_t)(m0 + row) * 2048 + hoff;
#pragma unroll
        for (int j = 0; j < 8; j++) {
            int c = c0 + j;
            CP_ASYNC16(sb + FM_QH + sw256(row, c << 4), qh + c * 8);
        }
    }

    const int krow = tid >> 2;
    const int kc0 = (tid & 3) << 2;
    const int vrow = tid >> 1;
    const int vc0 = (tid & 1) << 2;

#define FM_ISSUE(kt, buf) do {                                                  \
    uint32_t _st = sb + FM_STG0 + (buf) * FM_STAGE;                             \
    const __half* _kh = Kh + (size_t)((kt) + krow) * 2048 + hoff;               \
    _Pragma("unroll")                                                           \
    for (int _j = 0; _j < 4; _j++) {                                            \
        int _c = kc0 + _j;                                                      \
        CP_ASYNC16(_st + sw256(krow, _c << 4), _kh + _c * 8);                   \
    }                                                                           \
    const __half* _vh = VTh + (size_t)(hoff + vrow) * 4096 + (kt);              \
    _Pragma("unroll")                                                           \
    for (int _j = 0; _j < 4; _j++) {                                            \
        int _c = vc0 + _j;                                                      \
        uint32_t _sw = (uint32_t)(vrow * 128 + ((_c << 4) ^ ((vrow & 7) << 4)));\
        CP_ASYNC16(_st + 16384 + _sw, _vh + _c * 8);                            \
    }                                                                           \
} while (0)

    FM_ISSUE(0, 0);
    CP_COMMIT();

    float m0s = -1e30f, m1s = -1e30f, l0 = 0.f, l1 = 0.f;
    float o[16][4];
#pragma unroll
    for (int j = 0; j < 16; j++)
#pragma unroll
        for (int q = 0; q < 4; q++) o[j][q] = 0.f;

    const int NITER = 4096 / 64;
    for (int it = 0; it < NITER; it++) {
        const int buf = it & 1;
        CP_WAIT0();
        __syncthreads();
        if (it + 1 < NITER) {
            FM_ISSUE((it + 1) << 6, buf ^ 1);
            CP_COMMIT();
        }

        const uint32_t sKh = sb + FM_STG0 + buf * FM_STAGE;
        const uint32_t sVh = sKh + 16384;

        // ---- S = Q K^T ----
        float s[8][4];
#pragma unroll
        for (int j = 0; j < 8; j++)
#pragma unroll
            for (int q = 0; q < 4; q++) s[j][q] = 0.f;

#pragma unroll
        for (int ks = 0; ks < 8; ks++) {
            uint32_t ah[4], bh[4][4];
            {
                int row = qbase + (lane & 15);
                int kb = ks * 32 + ((lane >> 4) << 4);
                LDSM_X4(ah, sb + FM_QH + sw256(row, kb));
            }
#pragma unroll
            for (int pr = 0; pr < 4; pr++) {
                int row = pr * 16 + (lane & 7) + (((lane >> 4) & 1) << 3);
                int kb = ks * 32 + (((lane >> 3) & 1) << 4);
                LDSM_X4(bh[pr], sKh + sw256(row, kb));
            }
#pragma unroll
            for (int j = 0; j < 8; j++)
                MMAF16(s[j], ah, bh[j >> 1][(j & 1) << 1],
                       bh[j >> 1][((j & 1) << 1) + 1]);
        }

        // ---- online softmax (base-2) ----
        float mx0 = -1e30f, mx1 = -1e30f;
#pragma unroll
        for (int j = 0; j < 8; j++) {
            mx0 = fmaxf(mx0, fmaxf(s[j][0], s[j][1]));
            mx1 = fmaxf(mx1, fmaxf(s[j][2], s[j][3]));
        }
        mx0 = fmaxf(mx0, __shfl_xor_sync(0xffffffffu, mx0, 1));
        mx0 = fmaxf(mx0, __shfl_xor_sync(0xffffffffu, mx0, 2));
        mx1 = fmaxf(mx1, __shfl_xor_sync(0xffffffffu, mx1, 1));
        mx1 = fmaxf(mx1, __shfl_xor_sync(0xffffffffu, mx1, 2));
        float mn0 = fmaxf(m0s, mx0), mn1 = fmaxf(m1s, mx1);
        float corr0 = ex2(m0s - mn0), corr1 = ex2(m1s - mn1);
        m0s = mn0; m1s = mn1;

        float sum0 = 0.f, sum1 = 0.f;
        float p[8][4];
#pragma unroll
        for (int j = 0; j < 8; j++) {
            p[j][0] = ex2(s[j][0] - mn0);
            p[j][1] = ex2(s[j][1] - mn0);
            p[j][2] = ex2(s[j][2] - mn1);
            p[j][3] = ex2(s[j][3] - mn1);
            sum0 += p[j][0] + p[j][1];
            sum1 += p[j][2] + p[j][3];
        }
        sum0 += __shfl_xor_sync(0xffffffffu, sum0, 1);
        sum0 += __shfl_xor_sync(0xffffffffu, sum0, 2);
        sum1 += __shfl_xor_sync(0xffffffffu, sum1, 1);
        sum1 += __shfl_xor_sync(0xffffffffu, sum1, 2);
        l0 = l0 * corr0 + sum0;
        l1 = l1 * corr1 + sum1;

        // pack P -> fp16 A-fragments
        uint32_t pa[4][4];
#pragma unroll
        for (int kt = 0; kt < 4; kt++) {
#pragma unroll
            for (int t = 0; t < 2; t++) {
                int j = 2 * kt + t;
#pragma unroll
                for (int half = 0; half < 2; half++) {
                    __half2 hh = __floats2half2_rn(p[j][half * 2],
                                                   p[j][half * 2 + 1]);
                    pa[kt][t * 2 + half] = *(uint32_t*)&hh;
                }
            }
        }

#pragma unroll
        for (int j = 0; j < 16; j++) {
            o[j][0] *= corr0; o[j][1] *= corr0;
            o[j][2] *= corr1; o[j][3] *= corr1;
        }

        // ---- O += P V ----
#pragma unroll
        for (int kt = 0; kt < 4; kt++) {
#pragma unroll
            for (int prp = 0; prp < 4; prp++) {
                uint32_t bvh[2][4];
#pragma unroll
                for (int e = 0; e < 2; e++) {
                    int pr = prp * 2 + e;
                    int row = pr * 16 + (lane & 7) + (((lane >> 4) & 1) << 3);
                    int kb = kt * 32 + (((lane >> 3) & 1) << 4);
                    uint32_t sw = (uint32_t)(row * 128 + (kb ^ ((row & 7) << 4)));
                    LDSM_X4(bvh[e], sVh + sw);
                }
#pragma unroll
                for (int q = 0; q < 4; q++)
                    MMAF16(o[prp * 4 + q], pa[kt],
                           bvh[q >> 1][(q & 1) << 1],
                           bvh[q >> 1][((q & 1) << 1) + 1]);
            }
        }
    }

    // ---- epilogue: write fp16 O (A operand of O-proj) ----
    float inv0 = 1.0f / l0, inv1 = 1.0f / l1;
    int r0 = m0 + qbase + (lane >> 2);
#pragma unroll
    for (int j = 0; j < 16; j++) {
        int prp = j >> 2, e = (j >> 1) & 1, t = j & 1;
        int ntile = (prp * 2 + e) * 2 + t;
        int cc = hoff + ntile * 8 + ((lane & 3) << 1);
        {
            __half2 hh = __floats2half2_rn(o[j][0] * inv0, o[j][1] * inv0);
            *(uint32_t*)&Oh[(size_t)r0 * 2048 + cc] = *(uint32_t*)&hh;
        }
        {
            __half2 hh = __floats2half2_rn(o[j][2] * inv1, o[j][3] * inv1);
            *(uint32_t*)&Oh[(size_t)(r0 + 8) * 2048 + cc] = *(uint32_t*)&hh;
        }
    }
}

// ---------------------------------------------------------------------------
// Launch
// ---------------------------------------------------------------------------
extern "C" void kernel_launch(void* const* d_in, const int* in_sizes, int n_in,
                              void* d_out, int out_size) {
    const float* x  = (const float*)d_in[0];
    const float* wq = (const float*)d_in[1];
    const float* wk = (const float*)d_in[2];
    const float* wv = (const float*)d_in[3];
    const float* wo = (const float*)d_in[4];
    const float* qn = (const float*)d_in[5];
    const float* kn = (const float*)d_in[6];
    float* out = (float*)d_out;

    void *pq, *pk, *pv, *pxh, *pwh, *pqh, *pkh, *pvt;
    cudaGetSymbolAddress(&pq, g_Q);
    cudaGetSymbolAddress(&pk, g_K);
    cudaGetSymbolAddress(&pv, g_V);
    cudaGetSymbolAddress(&pxh, g_Xh);
    cudaGetSymbolAddress(&pwh, g_Wh);
    cudaGetSymbolAddress(&pqh, g_Qh);
    cudaGetSymbolAddress(&pkh, g_Kh);
    cudaGetSymbolAddress(&pvt, g_VTh);
    float* Q = (float*)pq;
    float* K = (float*)pk;
    float* V = (float*)pv;
    __half* Xh = (__half*)pxh;
    __half* Wh = (__half*)pwh;

    cudaFuncSetAttribute(gemm_mma, cudaFuncAttributeMaxDynamicSharedMemorySize, GM_SMEM);
    cudaFuncSetAttribute(flash_mma, cudaFuncAttributeMaxDynamicSharedMemorySize, FM_SMEM);

    const int M = 4096, D = 2048;
    const int nX4 = M * D / 4;
    const int nW4 = D * D / 4;
    dim3 gg(D / 128, M / 256);      // (16, 16)

    conv_h<<<(nX4 + 255) / 256, 256>>>(x, Xh, nX4);

    conv_h<<<(nW4 + 255) / 256, 256>>>(wq, Wh, nW4);
    gemm_mma<<<gg, 256, GM_SMEM>>>(Xh, Wh, Q);

    conv_h<<<(nW4 + 255) / 256, 256>>>(wk, Wh, nW4);
    gemm_mma<<<gg, 256, GM_SMEM>>>(Xh, Wh, K);

    conv_h<<<(nW4 + 255) / 256, 256>>>(wv, Wh, nW4);
    gemm_mma<<<gg, 256, GM_SMEM>>>(Xh, Wh, V);

    // fused rmsnorm (+ qscale = 1/sqrt(128) * log2(e) on Q)
    const float qscale = 0.08838834764831845f * 1.4426950408889634f;
    int nrows = M * 16;
    rmsnorm_h<<<nrows / 8, 256>>>(Q, qn, (__half*)pqh, nrows, qscale);
    rmsnorm_h<<<nrows / 8, 256>>>(K, kn, (__half*)pkh, nrows, 1.0f);
    transpose_h<<<dim3(M / 32, D / 32), 256>>>(V, (__half*)pvt);

    // flash writes fp16 O into Xh (A operand of O-proj)
    flash_mma<<<dim3(M / 128, 16), 256, FM_SMEM>>>(
        (__half*)pqh, (__half*)pkh, (__half*)pvt, Xh);

    conv_h<<<(nW4 + 255) / 256, 256>>>(wo, Wh, nW4);
    gemm_mma<<<gg, 256, GM_SMEM>>>(Xh, Wh, out);
}

// round 13
// speedup vs baseline: 1.1394x; 1.1394x over previous
#include <cuda_runtime.h>
#include <cuda_fp16.h>
#include <cstdint>
#include <math.h>

// ---------------- scratch (static device globals; no allocation) ----------
__device__ float g_Q[4096 * 2048];
__device__ float g_K[4096 * 2048];
__device__ float g_V[4096 * 2048];
__device__ __half g_Xh[4096 * 2048];     // x fp16; later attention-out fp16
__device__ __half g_Wh[2048 * 2048];     // weight fp16
__device__ __half g_Qh[4096 * 2048];
__device__ __half g_Kh[4096 * 2048];
__device__ __half g_VTh[2048 * 4096];    // [h*128+d][s], fp16

// ======================= portable PTX helpers (sm_80+) =====================
__device__ __forceinline__ uint32_t smem_u32(const void* p) {
    uint32_t a;
    asm("{ .reg .u64 t; cvta.to.shared.u64 t, %1; cvt.u32.u64 %0, t; }"
        : "=r"(a) : "l"(p));
    return a;
}
#define CP_ASYNC16(dst, src) \
    asm volatile("cp.async.cg.shared.global [%0], [%1], 16;" \
                 :: "r"(dst), "l"(src))
#define CP_COMMIT() asm volatile("cp.async.commit_group;")
#define CP_WAIT1()  asm volatile("cp.async.wait_group 1;")
#define CP_WAIT0()  asm volatile("cp.async.wait_group 0;")
#define LDSM_X4(r, addr) \
    asm volatile("ldmatrix.sync.aligned.m8n8.x4.shared.b16 {%0,%1,%2,%3}, [%4];" \
                 : "=r"((r)[0]), "=r"((r)[1]), "=r"((r)[2]), "=r"((r)[3]) \
                 : "r"(addr))
#define MMAF16(d, a, b0, b1) \
    asm volatile("mma.sync.aligned.m16n8k16.row.col.f32.f16.f16.f32 " \
                 "{%0,%1,%2,%3}, {%4,%5,%6,%7}, {%8,%9}, {%0,%1,%2,%3};" \
                 : "+f"((d)[0]), "+f"((d)[1]), "+f"((d)[2]), "+f"((d)[3]) \
                 : "r"((a)[0]), "r"((a)[1]), "r"((a)[2]), "r"((a)[3]), \
                   "r"(b0), "r"(b1))
__device__ __forceinline__ float ex2(float x) {
    float r;
    asm("ex2.approx.f32 %0, %1;" : "=f"(r) : "f"(x));
    return r;
}

// ---------------------------------------------------------------------------
// convert fp32 -> fp16
// ---------------------------------------------------------------------------
__global__ void __launch_bounds__(256) conv_h(const float* __restrict__ in,
                                              __half* __restrict__ out, int n4) {
    int i = blockIdx.x * blockDim.x + threadIdx.x;
    if (i >= n4) return;
    float4 v = ((const float4*)in)[i];
    union { __half b[4]; uint2 u; } H;
    H.b[0] = __float2half_rn(v.x);
    H.b[1] = __float2half_rn(v.y);
    H.b[2] = __float2half_rn(v.z);
    H.b[3] = __float2half_rn(v.w);
    ((uint2*)out)[i] = H.u;
}

// ---------------------------------------------------------------------------
// fused rmsnorm + scale + fp16 convert (one warp / (token,head) row)
// ---------------------------------------------------------------------------
__global__ void __launch_bounds__(256) rmsnorm_h(
    const float* __restrict__ X, const float* __restrict__ w,
    __half* __restrict__ out, int nrows, float scale) {
    int warp = (blockIdx.x * blockDim.x + threadIdx.x) >> 5;
    int lane = threadIdx.x & 31;
    if (warp >= nrows) return;

    float4 v = *(const float4*)&X[(size_t)warp * 128 + (lane << 2)];
    float ss = v.x * v.x + v.y * v.y + v.z * v.z + v.w * v.w;
#pragma unroll
    for (int off = 16; off > 0; off >>= 1)
        ss += __shfl_xor_sync(0xffffffffu, ss, off);

    float inv = rsqrtf(ss * (1.0f / 128.0f) + 1e-6f) * scale;
    float4 wv = *(const float4*)&w[lane << 2];
    union { __half b[4]; uint2 u; } H;
    H.b[0] = __float2half_rn(v.x * inv * wv.x);
    H.b[1] = __float2half_rn(v.y * inv * wv.y);
    H.b[2] = __float2half_rn(v.z * inv * wv.z);
    H.b[3] = __float2half_rn(v.w * inv * wv.w);
    ((uint2*)out)[(size_t)warp * 32 + lane] = H.u;
}

// ---------------------------------------------------------------------------
// transpose + fp16 convert V: [4096][2048] fp32 -> VT [2048][4096] fp16
// ---------------------------------------------------------------------------
__global__ void __launch_bounds__(256) transpose_h(
    const float* __restrict__ in, __half* __restrict__ th) {
    __shared__ float t[32][33];
    const int s0 = blockIdx.x << 5;
    const int c0 = blockIdx.y << 5;
    const int tx = threadIdx.x & 31;
    const int ty = threadIdx.x >> 5;
#pragma unroll
    for (int i = 0; i < 4; i++) {
        int r = (ty << 2) + i;
        t[r][tx] = in[(size_t)(s0 + r) * 2048 + c0 + tx];
    }
    __syncthreads();
#pragma unroll
    for (int i = 0; i < 4; i++) {
        int r = (ty << 2) + i;
        th[(size_t)(c0 + r) * 4096 + s0 + tx] = __float2half_rn(t[tx][r]);
    }
}

// ---------------------------------------------------------------------------
// gemm fp16 v5:  C = Ah * Bh^T, CTA tile 256x128 (46 B/MMA), 512 threads /
// 16 warps (warp tile 64x32 — same per-warp geometry as the proven round-11
// config), 1 CTA/SM = 16 warps/SM. K chunk 32 (64B rows), 3-stage cp.async,
// 1 sync/iter, NITER=64. Stage = A 16KB | B 8KB.
// ---------------------------------------------------------------------------
#define GMS      24576              // stage: A(16KB) + B(8KB)
#define GM_SMEM  (3 * GMS)          // 73728

__global__ void __launch_bounds__(512, 1) gemm_mma(
    const __half* __restrict__ Ah, const __half* __restrict__ Bh,
    float* __restrict__ C) {
    constexpr int Nd = 2048, Kd = 2048;
    extern __shared__ char smem[];
    const uint32_t sbase = smem_u32(smem);
    const int tid = threadIdx.x;
    const int lane = tid & 31;
    const int wid = tid >> 5;            // 0..15
    const int m0 = blockIdx.y << 8;      // 256-row tile
    const int n0 = blockIdx.x << 7;      // 128-col tile
    const int wm = (wid & 3) << 6;       // 0/64/128/192
    const int wn = (wid >> 2) << 5;      // 0/32/64/96

    float acc[4][4][4];
#pragma unroll
    for (int mi = 0; mi < 4; mi++)
#pragma unroll
        for (int ni = 0; ni < 4; ni++)
#pragma unroll
            for (int q = 0; q < 4; q++) acc[mi][ni][q] = 0.f;

    // loaders: A 256 rows x 4 chunks = 1024 chunks -> 2/thread;
    //          B 128 rows x 4 chunks = 512 chunks  -> 1/thread.
    const int arow = tid >> 1;           // 0..255
    const int ac0 = (tid & 1) << 1;      // chunk 0 or 2
    const int brow2 = tid >> 2;          // 0..127
    const int bc = tid & 3;              // chunk 0..3

    auto issue = [&](int it, int stage) {
        int kk = it << 5;
        const __half* pA = Ah + (size_t)(m0 + arow) * Kd + kk;
        uint32_t stA = sbase + stage * GMS + arow * 64;
#pragma unroll
        for (int j = 0; j < 2; j++) {
            int c = ac0 + j;
            uint32_t sw = (uint32_t)((c ^ ((arow >> 1) & 3)) << 4);
            CP_ASYNC16(stA + sw, pA + c * 8);
        }
        const __half* pB = Bh + (size_t)(n0 + brow2) * Kd + kk;
        uint32_t sw = (uint32_t)((bc ^ ((brow2 >> 1) & 3)) << 4);
        CP_ASYNC16(sbase + stage * GMS + 16384 + brow2 * 64 + sw, pB + bc * 8);
    };

    issue(0, 0); CP_COMMIT();
    issue(1, 1); CP_COMMIT();

    constexpr int NITER = 64;            // 2048 / 32
    int stage = 0, nstage = 2;
    for (int it = 0; it < NITER; it++) {
        if (it < NITER - 1) CP_WAIT1(); else CP_WAIT0();
        __syncthreads();
        if (it + 2 < NITER) { issue(it + 2, nstage); CP_COMMIT(); }

        const uint32_t sA = sbase + stage * GMS;
        const uint32_t sB = sA + 16384;

#pragma unroll
        for (int ks = 0; ks < 2; ks++) {
            uint32_t bh[2][4];
#pragma unroll
            for (int pr = 0; pr < 2; pr++) {
                int row = wn + pr * 16 + (lane & 7) + (((lane >> 4) & 1) << 3);
                int c = ks * 2 + ((lane >> 3) & 1);
                uint32_t off = (uint32_t)(row * 64 + ((c ^ ((row >> 1) & 3)) << 4));
                LDSM_X4(bh[pr], sB + off);
            }
#pragma unroll
            for (int mi = 0; mi < 4; mi++) {
                uint32_t ah[4];
                int row = wm + mi * 16 + (lane & 15);
                int c = ks * 2 + (lane >> 4);
                uint32_t off = (uint32_t)(row * 64 + ((c ^ ((row >> 1) & 3)) << 4));
                LDSM_X4(ah, sA + off);
#pragma unroll
                for (int ni = 0; ni < 4; ni++)
                    MMAF16(acc[mi][ni], ah,
                           bh[ni >> 1][(ni & 1) << 1],
                           bh[ni >> 1][((ni & 1) << 1) + 1]);
            }
        }
        stage = (stage == 2) ? 0 : stage + 1;
        nstage = (nstage == 2) ? 0 : nstage + 1;
    }

    // epilogue
#pragma unroll
    for (int mi = 0; mi < 4; mi++) {
        int r0 = m0 + wm + mi * 16 + (lane >> 2);
#pragma unroll
        for (int ni = 0; ni < 4; ni++) {
            int cc = n0 + wn + ni * 8 + ((lane & 3) << 1);
            *(float2*)&C[(size_t)r0 * Nd + cc] =
                make_float2(acc[mi][ni][0], acc[mi][ni][1]);
            *(float2*)&C[(size_t)(r0 + 8) * Nd + cc] =
                make_float2(acc[mi][ni][2], acc[mi][ni][3]);
        }
    }
}

// ---------------------------------------------------------------------------
// Flash attention fp16 1-pass (unchanged from round 11).
// ---------------------------------------------------------------------------
#define FM_QH    0
#define FM_STG0  32768
#define FM_STAGE 32768               // Kh 16KB | Vh 16KB
#define FM_SMEM  (32768 + 2 * FM_STAGE)   // 98304

__device__ __forceinline__ uint32_t sw256(int row, int kb) {
    return (uint32_t)(row * 256 + ((kb & 0x80) | ((kb ^ ((row & 7) << 4)) & 0x70)));
}

__global__ void __launch_bounds__(256, 1) flash_mma(
    const __half* __restrict__ Qh, const __half* __restrict__ Kh,
    const __half* __restrict__ VTh, __half* __restrict__ Oh) {
    extern __shared__ char smem[];
    const uint32_t sb = smem_u32(smem);
    const int tid = threadIdx.x;
    const int lane = tid & 31;
    const int wid = tid >> 5;
    const int h = blockIdx.y;
    const int m0 = blockIdx.x << 7;
    const int hoff = h << 7;
    const int qbase = wid << 4;

    // ---- load Q tile ----
    {
        int row = tid >> 1;
        int c0 = (tid & 1) << 3;
        const __half* qh = Qh + (size_t)(m0 + row) * 2048 + hoff;
#pragma unroll
        for (int j = 0; j < 8; j++) {
            int c = c0 + j;
            CP_ASYNC16(sb + FM_QH + sw256(row, c << 4), qh + c * 8);
        }
    }

    const int krow = tid >> 2;
    const int kc0 = (tid & 3) << 2;
    const int vrow = tid >> 1;
    const int vc0 = (tid & 1) << 2;

#define FM_ISSUE(kt, buf) do {                                                  \
    uint32_t _st = sb + FM_STG0 + (buf) * FM_STAGE;                             \
    const __half* _kh = Kh + (size_t)((kt) + krow) * 2048 + hoff;               \
    _Pragma("unroll")                                                           \
    for (int _j = 0; _j < 4; _j++) {                                            \
        int _c = kc0 + _j;                                                      \
        CP_ASYNC16(_st + sw256(krow, _c << 4), _kh + _c * 8);                   \
    }                                                                           \
    const __half* _vh = VTh + (size_t)(hoff + vrow) * 4096 + (kt);              \
    _Pragma("unroll")                                                           \
    for (int _j = 0; _j < 4; _j++) {                                            \
        int _c = vc0 + _j;                                                      \
        uint32_t _sw = (uint32_t)(vrow * 128 + ((_c << 4) ^ ((vrow & 7) << 4)));\
        CP_ASYNC16(_st + 16384 + _sw, _vh + _c * 8);                            \
    }                                                                           \
} while (0)

    FM_ISSUE(0, 0);
    CP_COMMIT();

    float m0s = -1e30f, m1s = -1e30f, l0 = 0.f, l1 = 0.f;
    float o[16][4];
#pragma unroll
    for (int j = 0; j < 16; j++)
#pragma unroll
        for (int q = 0; q < 4; q++) o[j][q] = 0.f;

    const int NITER = 4096 / 64;
    for (int it = 0; it < NITER; it++) {
        const int buf = it & 1;
        CP_WAIT0();
        __syncthreads();
        if (it + 1 < NITER) {
            FM_ISSUE((it + 1) << 6, buf ^ 1);
            CP_COMMIT();
        }

        const uint32_t sKh = sb + FM_STG0 + buf * FM_STAGE;
        const uint32_t sVh = sKh + 16384;

        // ---- S = Q K^T ----
        float s[8][4];
#pragma unroll
        for (int j = 0; j < 8; j++)
#pragma unroll
            for (int q = 0; q < 4; q++) s[j][q] = 0.f;

#pragma unroll
        for (int ks = 0; ks < 8; ks++) {
            uint32_t ah[4], bh[4][4];
            {
                int row = qbase + (lane & 15);
                int kb = ks * 32 + ((lane >> 4) << 4);
                LDSM_X4(ah, sb + FM_QH + sw256(row, kb));
            }
#pragma unroll
            for (int pr = 0; pr < 4; pr++) {
                int row = pr * 16 + (lane & 7) + (((lane >> 4) & 1) << 3);
                int kb = ks * 32 + (((lane >> 3) & 1) << 4);
                LDSM_X4(bh[pr], sKh + sw256(row, kb));
            }
#pragma unroll
            for (int j = 0; j < 8; j++)
                MMAF16(s[j], ah, bh[j >> 1][(j & 1) << 1],
                       bh[j >> 1][((j & 1) << 1) + 1]);
        }

        // ---- online softmax (base-2) ----
        float mx0 = -1e30f, mx1 = -1e30f;
#pragma unroll
        for (int j = 0; j < 8; j++) {
            mx0 = fmaxf(mx0, fmaxf(s[j][0], s[j][1]));
            mx1 = fmaxf(mx1, fmaxf(s[j][2], s[j][3]));
        }
        mx0 = fmaxf(mx0, __shfl_xor_sync(0xffffffffu, mx0, 1));
        mx0 = fmaxf(mx0, __shfl_xor_sync(0xffffffffu, mx0, 2));
        mx1 = fmaxf(mx1, __shfl_xor_sync(0xffffffffu, mx1, 1));
        mx1 = fmaxf(mx1, __shfl_xor_sync(0xffffffffu, mx1, 2));
        float mn0 = fmaxf(m0s, mx0), mn1 = fmaxf(m1s, mx1);
        float corr0 = ex2(m0s - mn0), corr1 = ex2(m1s - mn1);
        m0s = mn0; m1s = mn1;

        float sum0 = 0.f, sum1 = 0.f;
        float p[8][4];
#pragma unroll
        for (int j = 0; j < 8; j++) {
            p[j][0] = ex2(s[j][0] - mn0);
            p[j][1] = ex2(s[j][1] - mn0);
            p[j][2] = ex2(s[j][2] - mn1);
            p[j][3] = ex2(s[j][3] - mn1);
            sum0 += p[j][0] + p[j][1];
            sum1 += p[j][2] + p[j][3];
        }
        sum0 += __shfl_xor_sync(0xffffffffu, sum0, 1);
        sum0 += __shfl_xor_sync(0xffffffffu, sum0, 2);
        sum1 += __shfl_xor_sync(0xffffffffu, sum1, 1);
        sum1 += __shfl_xor_sync(0xffffffffu, sum1, 2);
        l0 = l0 * corr0 + sum0;
        l1 = l1 * corr1 + sum1;

        // pack P -> fp16 A-fragments
        uint32_t pa[4][4];
#pragma unroll
        for (int kt = 0; kt < 4; kt++) {
#pragma unroll
            for (int t = 0; t < 2; t++) {
                int j = 2 * kt + t;
#pragma unroll
                for (int half = 0; half < 2; half++) {
                    __half2 hh = __floats2half2_rn(p[j][half * 2],
                                                   p[j][half * 2 + 1]);
                    pa[kt][t * 2 + half] = *(uint32_t*)&hh;
                }
            }
        }

#pragma unroll
        for (int j = 0; j < 16; j++) {
            o[j][0] *= corr0; o[j][1] *= corr0;
            o[j][2] *= corr1; o[j][3] *= corr1;
        }

        // ---- O += P V ----
#pragma unroll
        for (int kt = 0; kt < 4; kt++) {
#pragma unroll
            for (int prp = 0; prp < 4; prp++) {
                uint32_t bvh[2][4];
#pragma unroll
                for (int e = 0; e < 2; e++) {
                    int pr = prp * 2 + e;
                    int row = pr * 16 + (lane & 7) + (((lane >> 4) & 1) << 3);
                    int kb = kt * 32 + (((lane >> 3) & 1) << 4);
                    uint32_t sw = (uint32_t)(row * 128 + (kb ^ ((row & 7) << 4)));
                    LDSM_X4(bvh[e], sVh + sw);
                }
#pragma unroll
                for (int q = 0; q < 4; q++)
                    MMAF16(o[prp * 4 + q], pa[kt],
                           bvh[q >> 1][(q & 1) << 1],
                           bvh[q >> 1][((q & 1) << 1) + 1]);
            }
        }
    }

    // ---- epilogue: write fp16 O (A operand of O-proj) ----
    float inv0 = 1.0f / l0, inv1 = 1.0f / l1;
    int r0 = m0 + qbase + (lane >> 2);
#pragma unroll
    for (int j = 0; j < 16; j++) {
        int prp = j >> 2, e = (j >> 1) & 1, t = j & 1;
        int ntile = (prp * 2 + e) * 2 + t;
        int cc = hoff + ntile * 8 + ((lane & 3) << 1);
        {
            __half2 hh = __floats2half2_rn(o[j][0] * inv0, o[j][1] * inv0);
            *(uint32_t*)&Oh[(size_t)r0 * 2048 + cc] = *(uint32_t*)&hh;
        }
        {
            __half2 hh = __floats2half2_rn(o[j][2] * inv1, o[j][3] * inv1);
            *(uint32_t*)&Oh[(size_t)(r0 + 8) * 2048 + cc] = *(uint32_t*)&hh;
        }
    }
}

// ---------------------------------------------------------------------------
// Launch
// ---------------------------------------------------------------------------
extern "C" void kernel_launch(void* const* d_in, const int* in_sizes, int n_in,
                              void* d_out, int out_size) {
    const float* x  = (const float*)d_in[0];
    const float* wq = (const float*)d_in[1];
    const float* wk = (const float*)d_in[2];
    const float* wv = (const float*)d_in[3];
    const float* wo = (const float*)d_in[4];
    const float* qn = (const float*)d_in[5];
    const float* kn = (const float*)d_in[6];
    float* out = (float*)d_out;

    void *pq, *pk, *pv, *pxh, *pwh, *pqh, *pkh, *pvt;
    cudaGetSymbolAddress(&pq, g_Q);
    cudaGetSymbolAddress(&pk, g_K);
    cudaGetSymbolAddress(&pv, g_V);
    cudaGetSymbolAddress(&pxh, g_Xh);
    cudaGetSymbolAddress(&pwh, g_Wh);
    cudaGetSymbolAddress(&pqh, g_Qh);
    cudaGetSymbolAddress(&pkh, g_Kh);
    cudaGetSymbolAddress(&pvt, g_VTh);
    float* Q = (float*)pq;
    float* K = (float*)pk;
    float* V = (float*)pv;
    __half* Xh = (__half*)pxh;
    __half* Wh = (__half*)pwh;

    cudaFuncSetAttribute(gemm_mma, cudaFuncAttributeMaxDynamicSharedMemorySize, GM_SMEM);
    cudaFuncSetAttribute(flash_mma, cudaFuncAttributeMaxDynamicSharedMemorySize, FM_SMEM);

    const int M = 4096, D = 2048;
    const int nX4 = M * D / 4;
    const int nW4 = D * D / 4;
    dim3 gg(D / 128, M / 256);      // (16, 16)

    conv_h<<<(nX4 + 255) / 256, 256>>>(x, Xh, nX4);

    conv_h<<<(nW4 + 255) / 256, 256>>>(wq, Wh, nW4);
    gemm_mma<<<gg, 512, GM_SMEM>>>(Xh, Wh, Q);

    conv_h<<<(nW4 + 255) / 256, 256>>>(wk, Wh, nW4);
    gemm_mma<<<gg, 512, GM_SMEM>>>(Xh, Wh, K);

    conv_h<<<(nW4 + 255) / 256, 256>>>(wv, Wh, nW4);
    gemm_mma<<<gg, 512, GM_SMEM>>>(Xh, Wh, V);

    // fused rmsnorm (+ qscale = 1/sqrt(128) * log2(e) on Q)
    const float qscale = 0.08838834764831845f * 1.4426950408889634f;
    int nrows = M * 16;
    rmsnorm_h<<<nrows / 8, 256>>>(Q, qn, (__half*)pqh, nrows, qscale);
    rmsnorm_h<<<nrows / 8, 256>>>(K, kn, (__half*)pkh, nrows, 1.0f);
    transpose_h<<<dim3(M / 32, D / 32), 256>>>(V, (__half*)pvt);

    // flash writes fp16 O into Xh (A operand of O-proj)
    flash_mma<<<dim3(M / 128, 16), 256, FM_SMEM>>>(
        (__half*)pqh, (__half*)pkh, (__half*)pvt, Xh);

    conv_h<<<(nW4 + 255) / 256, 256>>>(wo, Wh, nW4);
    gemm_mma<<<gg, 512, GM_SMEM>>>(Xh, Wh, out);
}

// round 14
// speedup vs baseline: 1.2213x; 1.0719x over previous
#include <cuda_runtime.h>
#include <cuda_fp16.h>
#include <cstdint>
#include <math.h>

// ---------------- scratch (static device globals; no allocation) ----------
__device__ float g_Q[4096 * 2048];
__device__ float g_K[4096 * 2048];
__device__ float g_V[4096 * 2048];
__device__ __half g_Xh[4096 * 2048];     // x fp16; later attention-out fp16
__device__ __half g_Wh[2048 * 2048];     // weight fp16
__device__ __half g_Qh[4096 * 2048];
__device__ __half g_Kh[4096 * 2048];
__device__ __half g_VTh[2048 * 4096];    // [h*128+d][s], fp16

// ======================= portable PTX helpers (sm_80+) =====================
__device__ __forceinline__ uint32_t smem_u32(const void* p) {
    uint32_t a;
    asm("{ .reg .u64 t; cvta.to.shared.u64 t, %1; cvt.u32.u64 %0, t; }"
        : "=r"(a) : "l"(p));
    return a;
}
#define CP_ASYNC16(dst, src) \
    asm volatile("cp.async.cg.shared.global [%0], [%1], 16;" \
                 :: "r"(dst), "l"(src))
#define CP_COMMIT() asm volatile("cp.async.commit_group;")
#define CP_WAIT1()  asm volatile("cp.async.wait_group 1;")
#define CP_WAIT0()  asm volatile("cp.async.wait_group 0;")
#define LDSM_X4(r, addr) \
    asm volatile("ldmatrix.sync.aligned.m8n8.x4.shared.b16 {%0,%1,%2,%3}, [%4];" \
                 : "=r"((r)[0]), "=r"((r)[1]), "=r"((r)[2]), "=r"((r)[3]) \
                 : "r"(addr))
#define MMAF16(d, a, b0, b1) \
    asm volatile("mma.sync.aligned.m16n8k16.row.col.f32.f16.f16.f32 " \
                 "{%0,%1,%2,%3}, {%4,%5,%6,%7}, {%8,%9}, {%0,%1,%2,%3};" \
                 : "+f"((d)[0]), "+f"((d)[1]), "+f"((d)[2]), "+f"((d)[3]) \
                 : "r"((a)[0]), "r"((a)[1]), "r"((a)[2]), "r"((a)[3]), \
                   "r"(b0), "r"(b1))
__device__ __forceinline__ float ex2(float x) {
    float r;
    asm("ex2.approx.f32 %0, %1;" : "=f"(r) : "f"(x));
    return r;
}

// ---------------------------------------------------------------------------
// convert fp32 -> fp16
// ---------------------------------------------------------------------------
__global__ void __launch_bounds__(256) conv_h(const float* __restrict__ in,
                                              __half* __restrict__ out, int n4) {
    int i = blockIdx.x * blockDim.x + threadIdx.x;
    if (i >= n4) return;
    float4 v = ((const float4*)in)[i];
    union { __half b[4]; uint2 u; } H;
    H.b[0] = __float2half_rn(v.x);
    H.b[1] = __float2half_rn(v.y);
    H.b[2] = __float2half_rn(v.z);
    H.b[3] = __float2half_rn(v.w);
    ((uint2*)out)[i] = H.u;
}

// ---------------------------------------------------------------------------
// fused rmsnorm + scale + fp16 convert (one warp / (token,head) row)
// ---------------------------------------------------------------------------
__global__ void __launch_bounds__(256) rmsnorm_h(
    const float* __restrict__ X, const float* __restrict__ w,
    __half* __restrict__ out, int nrows, float scale) {
    int warp = (blockIdx.x * blockDim.x + threadIdx.x) >> 5;
    int lane = threadIdx.x & 31;
    if (warp >= nrows) return;

    float4 v = *(const float4*)&X[(size_t)warp * 128 + (lane << 2)];
    float ss = v.x * v.x + v.y * v.y + v.z * v.z + v.w * v.w;
#pragma unroll
    for (int off = 16; off > 0; off >>= 1)
        ss += __shfl_xor_sync(0xffffffffu, ss, off);

    float inv = rsqrtf(ss * (1.0f / 128.0f) + 1e-6f) * scale;
    float4 wv = *(const float4*)&w[lane << 2];
    union { __half b[4]; uint2 u; } H;
    H.b[0] = __float2half_rn(v.x * inv * wv.x);
    H.b[1] = __float2half_rn(v.y * inv * wv.y);
    H.b[2] = __float2half_rn(v.z * inv * wv.z);
    H.b[3] = __float2half_rn(v.w * inv * wv.w);
    ((uint2*)out)[(size_t)warp * 32 + lane] = H.u;
}

// ---------------------------------------------------------------------------
// transpose + fp16 convert V: [4096][2048] fp32 -> VT [2048][4096] fp16
// ---------------------------------------------------------------------------
__global__ void __launch_bounds__(256) transpose_h(
    const float* __restrict__ in, __half* __restrict__ th) {
    __shared__ float t[32][33];
    const int s0 = blockIdx.x << 5;
    const int c0 = blockIdx.y << 5;
    const int tx = threadIdx.x & 31;
    const int ty = threadIdx.x >> 5;
#pragma unroll
    for (int i = 0; i < 4; i++) {
        int r = (ty << 2) + i;
        t[r][tx] = in[(size_t)(s0 + r) * 2048 + c0 + tx];
    }
    __syncthreads();
#pragma unroll
    for (int i = 0; i < 4; i++) {
        int r = (ty << 2) + i;
        th[(size_t)(c0 + r) * 4096 + s0 + tx] = __float2half_rn(t[tx][r]);
    }
}

// ---------------------------------------------------------------------------
// gemm fp16 (round-13 version): C = Ah * Bh^T, CTA 256x128, 512 threads /
// 16 warps (warp 64x32), K chunk 32, 3-stage cp.async, 1 sync/iter.
// ---------------------------------------------------------------------------
#define GMS      24576              // stage: A(16KB) + B(8KB)
#define GM_SMEM  (3 * GMS)          // 73728

__global__ void __launch_bounds__(512, 1) gemm_mma(
    const __half* __restrict__ Ah, const __half* __restrict__ Bh,
    float* __restrict__ C) {
    constexpr int Nd = 2048, Kd = 2048;
    extern __shared__ char smem[];
    const uint32_t sbase = smem_u32(smem);
    const int tid = threadIdx.x;
    const int lane = tid & 31;
    const int wid = tid >> 5;            // 0..15
    const int m0 = blockIdx.y << 8;
    const int n0 = blockIdx.x << 7;
    const int wm = (wid & 3) << 6;       // 0/64/128/192
    const int wn = (wid >> 2) << 5;      // 0/32/64/96

    float acc[4][4][4];
#pragma unroll
    for (int mi = 0; mi < 4; mi++)
#pragma unroll
        for (int ni = 0; ni < 4; ni++)
#pragma unroll
            for (int q = 0; q < 4; q++) acc[mi][ni][q] = 0.f;

    const int arow = tid >> 1;
    const int ac0 = (tid & 1) << 1;
    const int brow2 = tid >> 2;
    const int bc = tid & 3;

    auto issue = [&](int it, int stage) {
        int kk = it << 5;
        const __half* pA = Ah + (size_t)(m0 + arow) * Kd + kk;
        uint32_t stA = sbase + stage * GMS + arow * 64;
#pragma unroll
        for (int j = 0; j < 2; j++) {
            int c = ac0 + j;
            uint32_t sw = (uint32_t)((c ^ ((arow >> 1) & 3)) << 4);
            CP_ASYNC16(stA + sw, pA + c * 8);
        }
        const __half* pB = Bh + (size_t)(n0 + brow2) * Kd + kk;
        uint32_t sw = (uint32_t)((bc ^ ((brow2 >> 1) & 3)) << 4);
        CP_ASYNC16(sbase + stage * GMS + 16384 + brow2 * 64 + sw, pB + bc * 8);
    };

    issue(0, 0); CP_COMMIT();
    issue(1, 1); CP_COMMIT();

    constexpr int NITER = 64;
    int stage = 0, nstage = 2;
    for (int it = 0; it < NITER; it++) {
        if (it < NITER - 1) CP_WAIT1(); else CP_WAIT0();
        __syncthreads();
        if (it + 2 < NITER) { issue(it + 2, nstage); CP_COMMIT(); }

        const uint32_t sA = sbase + stage * GMS;
        const uint32_t sB = sA + 16384;

#pragma unroll
        for (int ks = 0; ks < 2; ks++) {
            uint32_t bh[2][4];
#pragma unroll
            for (int pr = 0; pr < 2; pr++) {
                int row = wn + pr * 16 + (lane & 7) + (((lane >> 4) & 1) << 3);
                int c = ks * 2 + ((lane >> 3) & 1);
                uint32_t off = (uint32_t)(row * 64 + ((c ^ ((row >> 1) & 3)) << 4));
                LDSM_X4(bh[pr], sB + off);
            }
#pragma unroll
            for (int mi = 0; mi < 4; mi++) {
                uint32_t ah[4];
                int row = wm + mi * 16 + (lane & 15);
                int c = ks * 2 + (lane >> 4);
                uint32_t off = (uint32_t)(row * 64 + ((c ^ ((row >> 1) & 3)) << 4));
                LDSM_X4(ah, sA + off);
#pragma unroll
                for (int ni = 0; ni < 4; ni++)
                    MMAF16(acc[mi][ni], ah,
                           bh[ni >> 1][(ni & 1) << 1],
                           bh[ni >> 1][((ni & 1) << 1) + 1]);
            }
        }
        stage = (stage == 2) ? 0 : stage + 1;
        nstage = (nstage == 2) ? 0 : nstage + 1;
    }

#pragma unroll
    for (int mi = 0; mi < 4; mi++) {
        int r0 = m0 + wm + mi * 16 + (lane >> 2);
#pragma unroll
        for (int ni = 0; ni < 4; ni++) {
            int cc = n0 + wn + ni * 8 + ((lane & 3) << 1);
            *(float2*)&C[(size_t)r0 * Nd + cc] =
                make_float2(acc[mi][ni][0], acc[mi][ni][1]);
            *(float2*)&C[(size_t)(r0 + 8) * Nd + cc] =
                make_float2(acc[mi][ni][2], acc[mi][ni][3]);
        }
    }
}

// ---------------------------------------------------------------------------
// Flash attention fp16 v2: 256 queries x one head per CTA, 512 threads /
// 16 warps (warp = 16 q-rows, unchanged geometry). K tiles of 64 keys,
// 2-stage cp.async — K/V bytes amortized over 2x the queries.
// Register trims: B-frags loaded per-pr, P packed per-kt.
// ---------------------------------------------------------------------------
#define FM_QH    0
#define FM_STG0  65536               // Q tile 256x256B = 64KB
#define FM_STAGE 32768               // Kh 16KB | Vh 16KB
#define FM_SMEM  (65536 + 2 * FM_STAGE)   // 131072

__device__ __forceinline__ uint32_t sw256(int row, int kb) {
    return (uint32_t)(row * 256 + ((kb & 0x80) | ((kb ^ ((row & 7) << 4)) & 0x70)));
}

__global__ void __launch_bounds__(512, 1) flash_mma(
    const __half* __restrict__ Qh, const __half* __restrict__ Kh,
    const __half* __restrict__ VTh, __half* __restrict__ Oh) {
    extern __shared__ char smem[];
    const uint32_t sb = smem_u32(smem);
    const int tid = threadIdx.x;
    const int lane = tid & 31;
    const int wid = tid >> 5;            // 0..15
    const int h = blockIdx.y;
    const int m0 = blockIdx.x << 8;      // 256-query block
    const int hoff = h << 7;
    const int qbase = wid << 4;          // warp's 16 q rows (0..240)

    // ---- load Q tile: 256 rows x 256B ----
    {
        int row = tid >> 1;              // 0..255
        int c0 = (tid & 1) << 3;
        const __half* qh = Qh + (size_t)(m0 + row) * 2048 + hoff;
#pragma unroll
        for (int j = 0; j < 8; j++) {
            int c = c0 + j;
            CP_ASYNC16(sb + FM_QH + sw256(row, c << 4), qh + c * 8);
        }
    }

    const int krow = tid >> 3;           // 0..63
    const int kc0 = (tid & 7) << 1;      // 2 chunks of 16
    const int vrow = tid >> 2;           // 0..127
    const int vc0 = (tid & 3) << 1;      // 2 chunks of 8

#define FM_ISSUE(kt, buf) do {                                                  \
    uint32_t _st = sb + FM_STG0 + (buf) * FM_STAGE;                             \
    const __half* _kh = Kh + (size_t)((kt) + krow) * 2048 + hoff;               \
    _Pragma("unroll")                                                           \
    for (int _j = 0; _j < 2; _j++) {                                            \
        int _c = kc0 + _j;                                                      \
        CP_ASYNC16(_st + sw256(krow, _c << 4), _kh + _c * 8);                   \
    }                                                                           \
    const __half* _vh = VTh + (size_t)(hoff + vrow) * 4096 + (kt);              \
    _Pragma("unroll")                                                           \
    for (int _j = 0; _j < 2; _j++) {                                            \
        int _c = vc0 + _j;                                                      \
        uint32_t _sw = (uint32_t)(vrow * 128 + ((_c << 4) ^ ((vrow & 7) << 4)));\
        CP_ASYNC16(_st + 16384 + _sw, _vh + _c * 8);                            \
    }                                                                           \
} while (0)

    FM_ISSUE(0, 0);
    CP_COMMIT();

    float m0s = -1e30f, m1s = -1e30f, l0 = 0.f, l1 = 0.f;
    float o[16][4];
#pragma unroll
    for (int j = 0; j < 16; j++)
#pragma unroll
        for (int q = 0; q < 4; q++) o[j][q] = 0.f;

    const int NITER = 4096 / 64;
    for (int it = 0; it < NITER; it++) {
        const int buf = it & 1;
        CP_WAIT0();
        __syncthreads();
        if (it + 1 < NITER) {
            FM_ISSUE((it + 1) << 6, buf ^ 1);
            CP_COMMIT();
        }

        const uint32_t sKh = sb + FM_STG0 + buf * FM_STAGE;
        const uint32_t sVh = sKh + 16384;

        // ---- S = Q K^T (B-frags loaded per-pr, consumed immediately) ----
        float s[8][4];
#pragma unroll
        for (int j = 0; j < 8; j++)
#pragma unroll
            for (int q = 0; q < 4; q++) s[j][q] = 0.f;

#pragma unroll
        for (int ks = 0; ks < 8; ks++) {
            uint32_t ah[4];
            {
                int row = qbase + (lane & 15);
                int kb = ks * 32 + ((lane >> 4) << 4);
                LDSM_X4(ah, sb + FM_QH + sw256(row, kb));
            }
#pragma unroll
            for (int pr = 0; pr < 4; pr++) {
                uint32_t bh[4];
                int row = pr * 16 + (lane & 7) + (((lane >> 4) & 1) << 3);
                int kb = ks * 32 + (((lane >> 3) & 1) << 4);
                LDSM_X4(bh, sKh + sw256(row, kb));
                MMAF16(s[2 * pr],     ah, bh[0], bh[1]);
                MMAF16(s[2 * pr + 1], ah, bh[2], bh[3]);
            }
        }

        // ---- online softmax (base-2) ----
        float mx0 = -1e30f, mx1 = -1e30f;
#pragma unroll
        for (int j = 0; j < 8; j++) {
            mx0 = fmaxf(mx0, fmaxf(s[j][0], s[j][1]));
            mx1 = fmaxf(mx1, fmaxf(s[j][2], s[j][3]));
        }
        mx0 = fmaxf(mx0, __shfl_xor_sync(0xffffffffu, mx0, 1));
        mx0 = fmaxf(mx0, __shfl_xor_sync(0xffffffffu, mx0, 2));
        mx1 = fmaxf(mx1, __shfl_xor_sync(0xffffffffu, mx1, 1));
        mx1 = fmaxf(mx1, __shfl_xor_sync(0xffffffffu, mx1, 2));
        float mn0 = fmaxf(m0s, mx0), mn1 = fmaxf(m1s, mx1);
        float corr0 = ex2(m0s - mn0), corr1 = ex2(m1s - mn1);
        m0s = mn0; m1s = mn1;

        float sum0 = 0.f, sum1 = 0.f;
#pragma unroll
        for (int j = 0; j < 8; j++) {
            s[j][0] = ex2(s[j][0] - mn0);
            s[j][1] = ex2(s[j][1] - mn0);
            s[j][2] = ex2(s[j][2] - mn1);
            s[j][3] = ex2(s[j][3] - mn1);
            sum0 += s[j][0] + s[j][1];
            sum1 += s[j][2] + s[j][3];
        }
        sum0 += __shfl_xor_sync(0xffffffffu, sum0, 1);
        sum0 += __shfl_xor_sync(0xffffffffu, sum0, 2);
        sum1 += __shfl_xor_sync(0xffffffffu, sum1, 1);
        sum1 += __shfl_xor_sync(0xffffffffu, sum1, 2);
        l0 = l0 * corr0 + sum0;
        l1 = l1 * corr1 + sum1;

#pragma unroll
        for (int j = 0; j < 16; j++) {
            o[j][0] *= corr0; o[j][1] *= corr0;
            o[j][2] *= corr1; o[j][3] *= corr1;
        }

        // ---- O += P V (P packed per-kt to limit live registers) ----
#pragma unroll
        for (int kt = 0; kt < 4; kt++) {
            uint32_t pa[4];
#pragma unroll
            for (int t = 0; t < 2; t++) {
                int j = 2 * kt + t;
#pragma unroll
                for (int half = 0; half < 2; half++) {
                    __half2 hh = __floats2half2_rn(s[j][half * 2],
                                                   s[j][half * 2 + 1]);
                    pa[t * 2 + half] = *(uint32_t*)&hh;
                }
            }
#pragma unroll
            for (int prp = 0; prp < 4; prp++) {
                uint32_t bvh[2][4];
#pragma unroll
                for (int e = 0; e < 2; e++) {
                    int pr = prp * 2 + e;
                    int row = pr * 16 + (lane & 7) + (((lane >> 4) & 1) << 3);
                    int kb = kt * 32 + (((lane >> 3) & 1) << 4);
                    uint32_t sw = (uint32_t)(row * 128 + (kb ^ ((row & 7) << 4)));
                    LDSM_X4(bvh[e], sVh + sw);
                }
#pragma unroll
                for (int q = 0; q < 4; q++)
                    MMAF16(o[prp * 4 + q], pa,
                           bvh[q >> 1][(q & 1) << 1],
                           bvh[q >> 1][((q & 1) << 1) + 1]);
            }
        }
    }

    // ---- epilogue: write fp16 O (A operand of O-proj) ----
    float inv0 = 1.0f / l0, inv1 = 1.0f / l1;
    int r0 = m0 + qbase + (lane >> 2);
#pragma unroll
    for (int j = 0; j < 16; j++) {
        int prp = j >> 2, e = (j >> 1) & 1, t = j & 1;
        int ntile = (prp * 2 + e) * 2 + t;
        int cc = hoff + ntile * 8 + ((lane & 3) << 1);
        {
            __half2 hh = __floats2half2_rn(o[j][0] * inv0, o[j][1] * inv0);
            *(uint32_t*)&Oh[(size_t)r0 * 2048 + cc] = *(uint32_t*)&hh;
        }
        {
            __half2 hh = __floats2half2_rn(o[j][2] * inv1, o[j][3] * inv1);
            *(uint32_t*)&Oh[(size_t)(r0 + 8) * 2048 + cc] = *(uint32_t*)&hh;
        }
    }
}

// ---------------------------------------------------------------------------
// Launch
// ---------------------------------------------------------------------------
extern "C" void kernel_launch(void* const* d_in, const int* in_sizes, int n_in,
                              void* d_out, int out_size) {
    const float* x  = (const float*)d_in[0];
    const float* wq = (const float*)d_in[1];
    const float* wk = (const float*)d_in[2];
    const float* wv = (const float*)d_in[3];
    const float* wo = (const float*)d_in[4];
    const float* qn = (const float*)d_in[5];
    const float* kn = (const float*)d_in[6];
    float* out = (float*)d_out;

    void *pq, *pk, *pv, *pxh, *pwh, *pqh, *pkh, *pvt;
    cudaGetSymbolAddress(&pq, g_Q);
    cudaGetSymbolAddress(&pk, g_K);
    cudaGetSymbolAddress(&pv, g_V);
    cudaGetSymbolAddress(&pxh, g_Xh);
    cudaGetSymbolAddress(&pwh, g_Wh);
    cudaGetSymbolAddress(&pqh, g_Qh);
    cudaGetSymbolAddress(&pkh, g_Kh);
    cudaGetSymbolAddress(&pvt, g_VTh);
    float* Q = (float*)pq;
    float* K = (float*)pk;
    float* V = (float*)pv;
    __half* Xh = (__half*)pxh;
    __half* Wh = (__half*)pwh;

    cudaFuncSetAttribute(gemm_mma, cudaFuncAttributeMaxDynamicSharedMemorySize, GM_SMEM);
    cudaFuncSetAttribute(flash_mma, cudaFuncAttributeMaxDynamicSharedMemorySize, FM_SMEM);

    const int M = 4096, D = 2048;
    const int nX4 = M * D / 4;
    const int nW4 = D * D / 4;
    dim3 gg(D / 128, M / 256);      // (16, 16)

    conv_h<<<(nX4 + 255) / 256, 256>>>(x, Xh, nX4);

    conv_h<<<(nW4 + 255) / 256, 256>>>(wq, Wh, nW4);
    gemm_mma<<<gg, 512, GM_SMEM>>>(Xh, Wh, Q);

    conv_h<<<(nW4 + 255) / 256, 256>>>(wk, Wh, nW4);
    gemm_mma<<<gg, 512, GM_SMEM>>>(Xh, Wh, K);

    conv_h<<<(nW4 + 255) / 256, 256>>>(wv, Wh, nW4);
    gemm_mma<<<gg, 512, GM_SMEM>>>(Xh, Wh, V);

    // fused rmsnorm (+ qscale = 1/sqrt(128) * log2(e) on Q)
    const float qscale = 0.08838834764831845f * 1.4426950408889634f;
    int nrows = M * 16;
    rmsnorm_h<<<nrows / 8, 256>>>(Q, qn, (__half*)pqh, nrows, qscale);
    rmsnorm_h<<<nrows / 8, 256>>>(K, kn, (__half*)pkh, nrows, 1.0f);
    transpose_h<<<dim3(M / 32, D / 32), 256>>>(V, (__half*)pvt);

    // flash writes fp16 O into Xh (A operand of O-proj); 256 queries/CTA
    flash_mma<<<dim3(M / 256, 16), 512, FM_SMEM>>>(
        (__half*)pqh, (__half*)pkh, (__half*)pvt, Xh);

    conv_h<<<(nW4 + 255) / 256, 256>>>(wo, Wh, nW4);
    gemm_mma<<<gg, 512, GM_SMEM>>>(Xh, Wh, out);
}

// round 15
// speedup vs baseline: 1.2494x; 1.0229x over previous
#include <cuda_runtime.h>
#include <cuda_fp16.h>
#include <cstdint>
#include <math.h>

// ---------------- scratch (static device globals; no allocation) ----------
__device__ __half g_Vh[4096 * 2048];     // V fp16 (pre-transpose)
__device__ __half g_Xh[4096 * 2048];     // x fp16; later attention-out fp16
__device__ __half g_Wh[2048 * 2048];     // weight fp16
__device__ __half g_Qh[4096 * 2048];
__device__ __half g_Kh[4096 * 2048];
__device__ __half g_VTh[2048 * 4096];    // [h*128+d][s], fp16

// ======================= portable PTX helpers (sm_80+) =====================
__device__ __forceinline__ uint32_t smem_u32(const void* p) {
    uint32_t a;
    asm("{ .reg .u64 t; cvta.to.shared.u64 t, %1; cvt.u32.u64 %0, t; }"
        : "=r"(a) : "l"(p));
    return a;
}
#define CP_ASYNC16(dst, src) \
    asm volatile("cp.async.cg.shared.global [%0], [%1], 16;" \
                 :: "r"(dst), "l"(src))
#define CP_COMMIT() asm volatile("cp.async.commit_group;")
#define CP_WAIT1()  asm volatile("cp.async.wait_group 1;")
#define CP_WAIT0()  asm volatile("cp.async.wait_group 0;")
#define LDSM_X4(r, addr) \
    asm volatile("ldmatrix.sync.aligned.m8n8.x4.shared.b16 {%0,%1,%2,%3}, [%4];" \
                 : "=r"((r)[0]), "=r"((r)[1]), "=r"((r)[2]), "=r"((r)[3]) \
                 : "r"(addr))
#define MMAF16(d, a, b0, b1) \
    asm volatile("mma.sync.aligned.m16n8k16.row.col.f32.f16.f16.f32 " \
                 "{%0,%1,%2,%3}, {%4,%5,%6,%7}, {%8,%9}, {%0,%1,%2,%3};" \
                 : "+f"((d)[0]), "+f"((d)[1]), "+f"((d)[2]), "+f"((d)[3]) \
                 : "r"((a)[0]), "r"((a)[1]), "r"((a)[2]), "r"((a)[3]), \
                   "r"(b0), "r"(b1))
__device__ __forceinline__ float ex2(float x) {
    float r;
    asm("ex2.approx.f32 %0, %1;" : "=f"(r) : "f"(x));
    return r;
}

// ---------------------------------------------------------------------------
// convert fp32 -> fp16
// ---------------------------------------------------------------------------
__global__ void __launch_bounds__(256) conv_h(const float* __restrict__ in,
                                              __half* __restrict__ out, int n4) {
    int i = blockIdx.x * blockDim.x + threadIdx.x;
    if (i >= n4) return;
    float4 v = ((const float4*)in)[i];
    union { __half b[4]; uint2 u; } H;
    H.b[0] = __float2half_rn(v.x);
    H.b[1] = __float2half_rn(v.y);
    H.b[2] = __float2half_rn(v.z);
    H.b[3] = __float2half_rn(v.w);
    ((uint2*)out)[i] = H.u;
}

// ---------------------------------------------------------------------------
// transpose fp16 V: [4096][2048] -> VT [2048][4096]
// ---------------------------------------------------------------------------
__global__ void __launch_bounds__(256) transpose_h16(
    const __half* __restrict__ in, __half* __restrict__ th) {
    __shared__ __half t[32][33];
    const int s0 = blockIdx.x << 5;
    const int c0 = blockIdx.y << 5;
    const int tx = threadIdx.x & 31;
    const int ty = threadIdx.x >> 5;
#pragma unroll
    for (int i = 0; i < 4; i++) {
        int r = (ty << 2) + i;
        t[r][tx] = in[(size_t)(s0 + r) * 2048 + c0 + tx];
    }
    __syncthreads();
#pragma unroll
    for (int i = 0; i < 4; i++) {
        int r = (ty << 2) + i;
        th[(size_t)(c0 + r) * 4096 + s0 + tx] = t[tx][r];
    }
}

// ---------------------------------------------------------------------------
// gemm fp16, CTA 256x128, 512 threads / 16 warps (warp 64x32), k-chunk 32,
// 3-stage cp.async, 1 sync/iter. Templated epilogue:
//  MODE 0: fp32 out.  MODE 1: fused per-head RMSNorm (+scale,+weights), fp16.
//  MODE 2: fp16 out.
// N-tile = 128 cols = exactly one head -> rmsnorm reduction is CTA-local.
// ---------------------------------------------------------------------------
#define GMS      24576              // stage: A(16KB) + B(8KB)
#define GM_SMEM  (3 * GMS + 4096)   // + reduction scratch 256 rows x 4 floats

template <int MODE>
__global__ void __launch_bounds__(512, 1) gemm_mma(
    const __half* __restrict__ Ah, const __half* __restrict__ Bh,
    const float* __restrict__ w, float scale, void* __restrict__ Cout) {
    constexpr int Nd = 2048, Kd = 2048;
    extern __shared__ char smem[];
    const uint32_t sbase = smem_u32(smem);
    const int tid = threadIdx.x;
    const int lane = tid & 31;
    const int wid = tid >> 5;            // 0..15
    const int m0 = blockIdx.y << 8;
    const int n0 = blockIdx.x << 7;
    const int wm = (wid & 3) << 6;       // 0/64/128/192
    const int wn = (wid >> 2) << 5;      // 0/32/64/96

    float acc[4][4][4];
#pragma unroll
    for (int mi = 0; mi < 4; mi++)
#pragma unroll
        for (int ni = 0; ni < 4; ni++)
#pragma unroll
            for (int q = 0; q < 4; q++) acc[mi][ni][q] = 0.f;

    const int arow = tid >> 1;
    const int ac0 = (tid & 1) << 1;
    const int brow2 = tid >> 2;
    const int bc = tid & 3;

    auto issue = [&](int it, int stage) {
        int kk = it << 5;
        const __half* pA = Ah + (size_t)(m0 + arow) * Kd + kk;
        uint32_t stA = sbase + stage * GMS + arow * 64;
#pragma unroll
        for (int j = 0; j < 2; j++) {
            int c = ac0 + j;
            uint32_t sw = (uint32_t)((c ^ ((arow >> 1) & 3)) << 4);
            CP_ASYNC16(stA + sw, pA + c * 8);
        }
        const __half* pB = Bh + (size_t)(n0 + brow2) * Kd + kk;
        uint32_t sw = (uint32_t)((bc ^ ((brow2 >> 1) & 3)) << 4);
        CP_ASYNC16(sbase + stage * GMS + 16384 + brow2 * 64 + sw, pB + bc * 8);
    };

    issue(0, 0); CP_COMMIT();
    issue(1, 1); CP_COMMIT();

    constexpr int NITER = 64;
    int stage = 0, nstage = 2;
    for (int it = 0; it < NITER; it++) {
        if (it < NITER - 1) CP_WAIT1(); else CP_WAIT0();
        __syncthreads();
        if (it + 2 < NITER) { issue(it + 2, nstage); CP_COMMIT(); }

        const uint32_t sA = sbase + stage * GMS;
        const uint32_t sB = sA + 16384;

#pragma unroll
        for (int ks = 0; ks < 2; ks++) {
            uint32_t bh[2][4];
#pragma unroll
            for (int pr = 0; pr < 2; pr++) {
                int row = wn + pr * 16 + (lane & 7) + (((lane >> 4) & 1) << 3);
                int c = ks * 2 + ((lane >> 3) & 1);
                uint32_t off = (uint32_t)(row * 64 + ((c ^ ((row >> 1) & 3)) << 4));
                LDSM_X4(bh[pr], sB + off);
            }
#pragma unroll
            for (int mi = 0; mi < 4; mi++) {
                uint32_t ah[4];
                int row = wm + mi * 16 + (lane & 15);
                int c = ks * 2 + (lane >> 4);
                uint32_t off = (uint32_t)(row * 64 + ((c ^ ((row >> 1) & 3)) << 4));
                LDSM_X4(ah, sA + off);
#pragma unroll
                for (int ni = 0; ni < 4; ni++)
                    MMAF16(acc[mi][ni], ah,
                           bh[ni >> 1][(ni & 1) << 1],
                           bh[ni >> 1][((ni & 1) << 1) + 1]);
            }
        }
        stage = (stage == 2) ? 0 : stage + 1;
        nstage = (nstage == 2) ? 0 : nstage + 1;
    }

    if (MODE == 0) {
        float* C = (float*)Cout;
#pragma unroll
        for (int mi = 0; mi < 4; mi++) {
            int r0 = m0 + wm + mi * 16 + (lane >> 2);
#pragma unroll
            for (int ni = 0; ni < 4; ni++) {
                int cc = n0 + wn + ni * 8 + ((lane & 3) << 1);
                *(float2*)&C[(size_t)r0 * Nd + cc] =
                    make_float2(acc[mi][ni][0], acc[mi][ni][1]);
                *(float2*)&C[(size_t)(r0 + 8) * Nd + cc] =
                    make_float2(acc[mi][ni][2], acc[mi][ni][3]);
            }
        }
    } else if (MODE == 2) {
        __half* C = (__half*)Cout;
#pragma unroll
        for (int mi = 0; mi < 4; mi++) {
            int r0 = m0 + wm + mi * 16 + (lane >> 2);
#pragma unroll
            for (int ni = 0; ni < 4; ni++) {
                int cc = n0 + wn + ni * 8 + ((lane & 3) << 1);
                __half2 h0 = __floats2half2_rn(acc[mi][ni][0], acc[mi][ni][1]);
                __half2 h1 = __floats2half2_rn(acc[mi][ni][2], acc[mi][ni][3]);
                *(uint32_t*)&C[(size_t)r0 * Nd + cc] = *(uint32_t*)&h0;
                *(uint32_t*)&C[(size_t)(r0 + 8) * Nd + cc] = *(uint32_t*)&h1;
            }
        }
    } else {
        // MODE 1: fused per-head RMSNorm + weight + scale, fp16 out.
        float* red = (float*)(smem + 3 * GMS);   // [256 rows][4 wn-groups]
        __syncthreads();
#pragma unroll
        for (int mi = 0; mi < 4; mi++) {
            float ss0 = 0.f, ss1 = 0.f;
#pragma unroll
            for (int ni = 0; ni < 4; ni++) {
                ss0 += acc[mi][ni][0] * acc[mi][ni][0]
                     + acc[mi][ni][1] * acc[mi][ni][1];
                ss1 += acc[mi][ni][2] * acc[mi][ni][2]
                     + acc[mi][ni][3] * acc[mi][ni][3];
            }
            ss0 += __shfl_xor_sync(0xffffffffu, ss0, 1);
            ss0 += __shfl_xor_sync(0xffffffffu, ss0, 2);
            ss1 += __shfl_xor_sync(0xffffffffu, ss1, 1);
            ss1 += __shfl_xor_sync(0xffffffffu, ss1, 2);
            if ((lane & 3) == 0) {
                int r = wm + mi * 16 + (lane >> 2);
                red[r * 4 + (wid >> 2)] = ss0;
                red[(r + 8) * 4 + (wid >> 2)] = ss1;
            }
        }
        __syncthreads();
        __half* C = (__half*)Cout;
#pragma unroll
        for (int mi = 0; mi < 4; mi++) {
            int rl = wm + mi * 16 + (lane >> 2);
            float s0 = red[rl * 4] + red[rl * 4 + 1]
                     + red[rl * 4 + 2] + red[rl * 4 + 3];
            float s1 = red[(rl + 8) * 4] + red[(rl + 8) * 4 + 1]
                     + red[(rl + 8) * 4 + 2] + red[(rl + 8) * 4 + 3];
            float inv0 = rsqrtf(s0 * (1.0f / 128.0f) + 1e-6f) * scale;
            float inv1 = rsqrtf(s1 * (1.0f / 128.0f) + 1e-6f) * scale;
            int r0 = m0 + rl;
#pragma unroll
            for (int ni = 0; ni < 4; ni++) {
                int d = wn + ni * 8 + ((lane & 3) << 1);
                float w0 = w[d], w1 = w[d + 1];
                __half2 h0 = __floats2half2_rn(acc[mi][ni][0] * inv0 * w0,
                                               acc[mi][ni][1] * inv0 * w1);
                __half2 h1 = __floats2half2_rn(acc[mi][ni][2] * inv1 * w0,
                                               acc[mi][ni][3] * inv1 * w1);
                *(uint32_t*)&C[(size_t)r0 * Nd + n0 + d] = *(uint32_t*)&h0;
                *(uint32_t*)&C[(size_t)(r0 + 8) * Nd + n0 + d] = *(uint32_t*)&h1;
            }
        }
    }
}

// ---------------------------------------------------------------------------
// Flash attention fp16 (round-14 version): 256 queries x one head per CTA,
// 512 threads / 16 warps. K tiles of 64 keys, 2-stage cp.async.
// ---------------------------------------------------------------------------
#define FM_QH    0
#define FM_STG0  65536               // Q tile 256x256B = 64KB
#define FM_STAGE 32768               // Kh 16KB | Vh 16KB
#define FM_SMEM  (65536 + 2 * FM_STAGE)   // 131072

__device__ __forceinline__ uint32_t sw256(int row, int kb) {
    return (uint32_t)(row * 256 + ((kb & 0x80) | ((kb ^ ((row & 7) << 4)) & 0x70)));
}

__global__ void __launch_bounds__(512, 1) flash_mma(
    const __half* __restrict__ Qh, const __half* __restrict__ Kh,
    const __half* __restrict__ VTh, __half* __restrict__ Oh) {
    extern __shared__ char smem[];
    const uint32_t sb = smem_u32(smem);
    const int tid = threadIdx.x;
    const int lane = tid & 31;
    const int wid = tid >> 5;
    const int h = blockIdx.y;
    const int m0 = blockIdx.x << 8;
    const int hoff = h << 7;
    const int qbase = wid << 4;

    {
        int row = tid >> 1;
        int c0 = (tid & 1) << 3;
        const __half* qh = Qh + (size_t)(m0 + row) * 2048 + hoff;
#pragma unroll
        for (int j = 0; j < 8; j++) {
            int c = c0 + j;
            CP_ASYNC16(sb + FM_QH + sw256(row, c << 4), qh + c * 8);
        }
    }

    const int krow = tid >> 3;
    const int kc0 = (tid & 7) << 1;
    const int vrow = tid >> 2;
    const int vc0 = (tid & 3) << 1;

#define FM_ISSUE(kt, buf) do {                                                  \
    uint32_t _st = sb + FM_STG0 + (buf) * FM_STAGE;                             \
    const __half* _kh = Kh + (size_t)((kt) + krow) * 2048 + hoff;               \
    _Pragma("unroll")                                                           \
    for (int _j = 0; _j < 2; _j++) {                                            \
        int _c = kc0 + _j;                                                      \
        CP_ASYNC16(_st + sw256(krow, _c << 4), _kh + _c * 8);                   \
    }                                                                           \
    const __half* _vh = VTh + (size_t)(hoff + vrow) * 4096 + (kt);              \
    _Pragma("unroll")                                                           \
    for (int _j = 0; _j < 2; _j++) {                                            \
        int _c = vc0 + _j;                                                      \
        uint32_t _sw = (uint32_t)(vrow * 128 + ((_c << 4) ^ ((vrow & 7) << 4)));\
        CP_ASYNC16(_st + 16384 + _sw, _vh + _c * 8);                            \
    }                                                                           \
} while (0)

    FM_ISSUE(0, 0);
    CP_COMMIT();

    float m0s = -1e30f, m1s = -1e30f, l0 = 0.f, l1 = 0.f;
    float o[16][4];
#pragma unroll
    for (int j = 0; j < 16; j++)
#pragma unroll
        for (int q = 0; q < 4; q++) o[j][q] = 0.f;

    const int NITER = 4096 / 64;
    for (int it = 0; it < NITER; it++) {
        const int buf = it & 1;
        CP_WAIT0();
        __syncthreads();
        if (it + 1 < NITER) {
            FM_ISSUE((it + 1) << 6, buf ^ 1);
            CP_COMMIT();
        }

        const uint32_t sKh = sb + FM_STG0 + buf * FM_STAGE;
        const uint32_t sVh = sKh + 16384;

        float s[8][4];
#pragma unroll
        for (int j = 0; j < 8; j++)
#pragma unroll
            for (int q = 0; q < 4; q++) s[j][q] = 0.f;

#pragma unroll
        for (int ks = 0; ks < 8; ks++) {
            uint32_t ah[4];
            {
                int row = qbase + (lane & 15);
                int kb = ks * 32 + ((lane >> 4) << 4);
                LDSM_X4(ah, sb + FM_QH + sw256(row, kb));
            }
#pragma unroll
            for (int pr = 0; pr < 4; pr++) {
                uint32_t bh[4];
                int row = pr * 16 + (lane & 7) + (((lane >> 4) & 1) << 3);
                int kb = ks * 32 + (((lane >> 3) & 1) << 4);
                LDSM_X4(bh, sKh + sw256(row, kb));
                MMAF16(s[2 * pr],     ah, bh[0], bh[1]);
                MMAF16(s[2 * pr + 1], ah, bh[2], bh[3]);
            }
        }

        float mx0 = -1e30f, mx1 = -1e30f;
#pragma unroll
        for (int j = 0; j < 8; j++) {
            mx0 = fmaxf(mx0, fmaxf(s[j][0], s[j][1]));
            mx1 = fmaxf(mx1, fmaxf(s[j][2], s[j][3]));
        }
        mx0 = fmaxf(mx0, __shfl_xor_sync(0xffffffffu, mx0, 1));
        mx0 = fmaxf(mx0, __shfl_xor_sync(0xffffffffu, mx0, 2));
        mx1 = fmaxf(mx1, __shfl_xor_sync(0xffffffffu, mx1, 1));
        mx1 = fmaxf(mx1, __shfl_xor_sync(0xffffffffu, mx1, 2));
        float mn0 = fmaxf(m0s, mx0), mn1 = fmaxf(m1s, mx1);
        float corr0 = ex2(m0s - mn0), corr1 = ex2(m1s - mn1);
        m0s = mn0; m1s = mn1;

        float sum0 = 0.f, sum1 = 0.f;
#pragma unroll
        for (int j = 0; j < 8; j++) {
            s[j][0] = ex2(s[j][0] - mn0);
            s[j][1] = ex2(s[j][1] - mn0);
            s[j][2] = ex2(s[j][2] - mn1);
            s[j][3] = ex2(s[j][3] - mn1);
            sum0 += s[j][0] + s[j][1];
            sum1 += s[j][2] + s[j][3];
        }
        sum0 += __shfl_xor_sync(0xffffffffu, sum0, 1);
        sum0 += __shfl_xor_sync(0xffffffffu, sum0, 2);
        sum1 += __shfl_xor_sync(0xffffffffu, sum1, 1);
        sum1 += __shfl_xor_sync(0xffffffffu, sum1, 2);
        l0 = l0 * corr0 + sum0;
        l1 = l1 * corr1 + sum1;

#pragma unroll
        for (int j = 0; j < 16; j++) {
            o[j][0] *= corr0; o[j][1] *= corr0;
            o[j][2] *= corr1; o[j][3] *= corr1;
        }

#pragma unroll
        for (int kt = 0; kt < 4; kt++) {
            uint32_t pa[4];
#pragma unroll
            for (int t = 0; t < 2; t++) {
                int j = 2 * kt + t;
#pragma unroll
                for (int half = 0; half < 2; half++) {
                    __half2 hh = __floats2half2_rn(s[j][half * 2],
                                                   s[j][half * 2 + 1]);
                    pa[t * 2 + half] = *(uint32_t*)&hh;
                }
            }
#pragma unroll
            for (int prp = 0; prp < 4; prp++) {
                uint32_t bvh[2][4];
#pragma unroll
                for (int e = 0; e < 2; e++) {
                    int pr = prp * 2 + e;
                    int row = pr * 16 + (lane & 7) + (((lane >> 4) & 1) << 3);
                    int kb = kt * 32 + (((lane >> 3) & 1) << 4);
                    uint32_t sw = (uint32_t)(row * 128 + (kb ^ ((row & 7) << 4)));
                    LDSM_X4(bvh[e], sVh + sw);
                }
#pragma unroll
                for (int q = 0; q < 4; q++)
                    MMAF16(o[prp * 4 + q], pa,
                           bvh[q >> 1][(q & 1) << 1],
                           bvh[q >> 1][((q & 1) << 1) + 1]);
            }
        }
    }

    float inv0 = 1.0f / l0, inv1 = 1.0f / l1;
    int r0 = m0 + qbase + (lane >> 2);
#pragma unroll
    for (int j = 0; j < 16; j++) {
        int prp = j >> 2, e = (j >> 1) & 1, t = j & 1;
        int ntile = (prp * 2 + e) * 2 + t;
        int cc = hoff + ntile * 8 + ((lane & 3) << 1);
        {
            __half2 hh = __floats2half2_rn(o[j][0] * inv0, o[j][1] * inv0);
            *(uint32_t*)&Oh[(size_t)r0 * 2048 + cc] = *(uint32_t*)&hh;
        }
        {
            __half2 hh = __floats2half2_rn(o[j][2] * inv1, o[j][3] * inv1);
            *(uint32_t*)&Oh[(size_t)(r0 + 8) * 2048 + cc] = *(uint32_t*)&hh;
        }
    }
}

// ---------------------------------------------------------------------------
// Launch
// ---------------------------------------------------------------------------
extern "C" void kernel_launch(void* const* d_in, const int* in_sizes, int n_in,
                              void* d_out, int out_size) {
    const float* x  = (const float*)d_in[0];
    const float* wq = (const float*)d_in[1];
    const float* wk = (const float*)d_in[2];
    const float* wv = (const float*)d_in[3];
    const float* wo = (const float*)d_in[4];
    const float* qn = (const float*)d_in[5];
    const float* kn = (const float*)d_in[6];
    float* out = (float*)d_out;

    void *pvh, *pxh, *pwh, *pqh, *pkh, *pvt;
    cudaGetSymbolAddress(&pvh, g_Vh);
    cudaGetSymbolAddress(&pxh, g_Xh);
    cudaGetSymbolAddress(&pwh, g_Wh);
    cudaGetSymbolAddress(&pqh, g_Qh);
    cudaGetSymbolAddress(&pkh, g_Kh);
    cudaGetSymbolAddress(&pvt, g_VTh);
    __half* Vh = (__half*)pvh;
    __half* Xh = (__half*)pxh;
    __half* Wh = (__half*)pwh;

    cudaFuncSetAttribute(gemm_mma<0>, cudaFuncAttributeMaxDynamicSharedMemorySize, GM_SMEM);
    cudaFuncSetAttribute(gemm_mma<1>, cudaFuncAttributeMaxDynamicSharedMemorySize, GM_SMEM);
    cudaFuncSetAttribute(gemm_mma<2>, cudaFuncAttributeMaxDynamicSharedMemorySize, GM_SMEM);
    cudaFuncSetAttribute(flash_mma, cudaFuncAttributeMaxDynamicSharedMemorySize, FM_SMEM);

    const int M = 4096, D = 2048;
    const int nX4 = M * D / 4;
    const int nW4 = D * D / 4;
    dim3 gg(D / 128, M / 256);      // (16, 16)

    const float qscale = 0.08838834764831845f * 1.4426950408889634f;

    conv_h<<<(nX4 + 255) / 256, 256>>>(x, Xh, nX4);

    conv_h<<<(nW4 + 255) / 256, 256>>>(wq, Wh, nW4);
    gemm_mma<1><<<gg, 512, GM_SMEM>>>(Xh, Wh, qn, qscale, pqh);

    conv_h<<<(nW4 + 255) / 256, 256>>>(wk, Wh, nW4);
    gemm_mma<1><<<gg, 512, GM_SMEM>>>(Xh, Wh, kn, 1.0f, pkh);

    conv_h<<<(nW4 + 255) / 256, 256>>>(wv, Wh, nW4);
    gemm_mma<2><<<gg, 512, GM_SMEM>>>(Xh, Wh, nullptr, 1.0f, pvh);

    transpose_h16<<<dim3(M / 32, D / 32), 256>>>(Vh, (__half*)pvt);

    // flash writes fp16 O into Xh (A operand of O-proj); 256 queries/CTA
    flash_mma<<<dim3(M / 256, 16), 512, FM_SMEM>>>(
        (__half*)pqh, (__half*)pkh, (__half*)pvt, Xh);

    conv_h<<<(nW4 + 255) / 256, 256>>>(wo, Wh, nW4);
    gemm_mma<0><<<gg, 512, GM_SMEM>>>(Xh, Wh, nullptr, 1.0f, out);
}

// round 16
// speedup vs baseline: 1.2917x; 1.0339x over previous
#include <cuda_runtime.h>
#include <cuda_fp16.h>
#include <cstdint>
#include <math.h>

// ---------------- scratch (static device globals; no allocation) ----------
__device__ __half g_Xh[4096 * 2048];        // x fp16; later attention-out fp16
__device__ __half g_W4[4 * 2048 * 2048];    // wq|wk|wv|wo fp16
__device__ __half g_Qh[4096 * 2048];
__device__ __half g_Kh[4096 * 2048];
__device__ __half g_VTh[2048 * 4096];       // [h*128+d][s], fp16

// ======================= portable PTX helpers (sm_80+) =====================
__device__ __forceinline__ uint32_t smem_u32(const void* p) {
    uint32_t a;
    asm("{ .reg .u64 t; cvta.to.shared.u64 t, %1; cvt.u32.u64 %0, t; }"
        : "=r"(a) : "l"(p));
    return a;
}
#define CP_ASYNC16(dst, src) \
    asm volatile("cp.async.cg.shared.global [%0], [%1], 16;" \
                 :: "r"(dst), "l"(src))
#define CP_COMMIT() asm volatile("cp.async.commit_group;")
#define CP_WAIT0()  asm volatile("cp.async.wait_group 0;")
#define LDSM_X4(r, addr) \
    asm volatile("ldmatrix.sync.aligned.m8n8.x4.shared.b16 {%0,%1,%2,%3}, [%4];" \
                 : "=r"((r)[0]), "=r"((r)[1]), "=r"((r)[2]), "=r"((r)[3]) \
                 : "r"(addr))
#define MMAF16(d, a, b0, b1) \
    asm volatile("mma.sync.aligned.m16n8k16.row.col.f32.f16.f16.f32 " \
                 "{%0,%1,%2,%3}, {%4,%5,%6,%7}, {%8,%9}, {%0,%1,%2,%3};" \
                 : "+f"((d)[0]), "+f"((d)[1]), "+f"((d)[2]), "+f"((d)[3]) \
                 : "r"((a)[0]), "r"((a)[1]), "r"((a)[2]), "r"((a)[3]), \
                   "r"(b0), "r"(b1))
__device__ __forceinline__ float ex2(float x) {
    float r;
    asm("ex2.approx.f32 %0, %1;" : "=f"(r) : "f"(x));
    return r;
}

// ---------------------------------------------------------------------------
// convert fp32 -> fp16 (x)
// ---------------------------------------------------------------------------
__global__ void __launch_bounds__(256) conv_h(const float* __restrict__ in,
                                              __half* __restrict__ out, int n4) {
    int i = blockIdx.x * blockDim.x + threadIdx.x;
    if (i >= n4) return;
    float4 v = ((const float4*)in)[i];
    union { __half b[4]; uint2 u; } H;
    H.b[0] = __float2half_rn(v.x);
    H.b[1] = __float2half_rn(v.y);
    H.b[2] = __float2half_rn(v.z);
    H.b[3] = __float2half_rn(v.w);
    ((uint2*)out)[i] = H.u;
}

// ---------------------------------------------------------------------------
// convert all 4 weights fp32 -> fp16 into one buffer (1 launch)
// ---------------------------------------------------------------------------
__global__ void __launch_bounds__(256) conv_w4(
    const float* __restrict__ w0, const float* __restrict__ w1,
    const float* __restrict__ w2, const float* __restrict__ w3,
    __half* __restrict__ out) {
    int i = blockIdx.x * blockDim.x + threadIdx.x;  // uint2 index, 4 x 1M
    int seg = i >> 20;
    int loc = i & 0xFFFFF;
    const float* src = (seg == 0) ? w0 : (seg == 1) ? w1 : (seg == 2) ? w2 : w3;
    float4 v = ((const float4*)src)[loc];
    union { __half b[4]; uint2 u; } H;
    H.b[0] = __float2half_rn(v.x);
    H.b[1] = __float2half_rn(v.y);
    H.b[2] = __float2half_rn(v.z);
    H.b[3] = __float2half_rn(v.w);
    ((uint2*)out)[i] = H.u;
}

// ---------------------------------------------------------------------------
// gemm fp16, CTA 256x128, 512 threads / 16 warps (warp 64x32), K chunk 64
// (128B rows, SW128 swizzle c ^ (row&7)), 2-stage cp.async, 1 sync/iter,
// NITER=32. Templated epilogue:
//  MODE 0: fp32 out.  MODE 1: fused per-head RMSNorm (+scale,+weights), fp16.
//  MODE 3: fp16 transposed out (VT[col][row], stride 4096).
// ---------------------------------------------------------------------------
#define GMS      49152              // stage: A(32KB) + B(16KB)
#define GM_SMEM  (2 * GMS + 4096)   // + reduction scratch

template <int MODE>
__global__ void __launch_bounds__(512, 1) gemm_mma(
    const __half* __restrict__ Ah, const __half* __restrict__ Bh,
    const float* __restrict__ w, float scale, void* __restrict__ Cout) {
    constexpr int Nd = 2048, Kd = 2048;
    extern __shared__ char smem[];
    const uint32_t sbase = smem_u32(smem);
    const int tid = threadIdx.x;
    const int lane = tid & 31;
    const int wid = tid >> 5;            // 0..15
    const int m0 = blockIdx.y << 8;
    const int n0 = blockIdx.x << 7;
    const int wm = (wid & 3) << 6;       // 0/64/128/192
    const int wn = (wid >> 2) << 5;      // 0/32/64/96

    float acc[4][4][4];
#pragma unroll
    for (int mi = 0; mi < 4; mi++)
#pragma unroll
        for (int ni = 0; ni < 4; ni++)
#pragma unroll
            for (int q = 0; q < 4; q++) acc[mi][ni][q] = 0.f;

    // loaders (128B rows, 8 chunks of 16B, swizzle c ^ (row&7)):
    // A: 256 rows, 2 threads/row, 4 chunks each. B: 128 rows, 4 thr/row, 2 each.
    const int arow = tid >> 1;
    const int ac0 = (tid & 1) << 2;
    const int brow = tid >> 2;
    const int bc0 = (tid & 3) << 1;

    auto issue = [&](int it, int stage) {
        int kk = it << 6;
        const __half* pA = Ah + (size_t)(m0 + arow) * Kd + kk;
        uint32_t stA = sbase + stage * GMS + arow * 128;
#pragma unroll
        for (int j = 0; j < 4; j++) {
            int c = ac0 + j;
            CP_ASYNC16(stA + ((uint32_t)(c ^ (arow & 7)) << 4), pA + c * 8);
        }
        const __half* pB = Bh + (size_t)(n0 + brow) * Kd + kk;
        uint32_t stB = sbase + stage * GMS + 32768 + brow * 128;
#pragma unroll
        for (int j = 0; j < 2; j++) {
            int c = bc0 + j;
            CP_ASYNC16(stB + ((uint32_t)(c ^ (brow & 7)) << 4), pB + c * 8);
        }
    };

    issue(0, 0); CP_COMMIT();

    constexpr int NITER = 32;            // 2048 / 64
    for (int it = 0; it < NITER; it++) {
        const int stage = it & 1;
        CP_WAIT0();
        __syncthreads();
        if (it + 1 < NITER) { issue(it + 1, stage ^ 1); CP_COMMIT(); }

        const uint32_t sA = sbase + stage * GMS;
        const uint32_t sB = sA + 32768;

#pragma unroll
        for (int ks = 0; ks < 4; ks++) {
            uint32_t bh[2][4];
#pragma unroll
            for (int pr = 0; pr < 2; pr++) {
                int row = wn + pr * 16 + (lane & 7) + (((lane >> 4) & 1) << 3);
                int c = ks * 2 + ((lane >> 3) & 1);
                uint32_t off = (uint32_t)(row * 128 + ((c ^ (row & 7)) << 4));
                LDSM_X4(bh[pr], sB + off);
            }
#pragma unroll
            for (int mi = 0; mi < 4; mi++) {
                uint32_t ah[4];
                int row = wm + mi * 16 + (lane & 15);
                int c = ks * 2 + (lane >> 4);
                uint32_t off = (uint32_t)(row * 128 + ((c ^ (row & 7)) << 4));
                LDSM_X4(ah, sA + off);
#pragma unroll
                for (int ni = 0; ni < 4; ni++)
                    MMAF16(acc[mi][ni], ah,
                           bh[ni >> 1][(ni & 1) << 1],
                           bh[ni >> 1][((ni & 1) << 1) + 1]);
            }
        }
    }

    if (MODE == 0) {
        float* C = (float*)Cout;
#pragma unroll
        for (int mi = 0; mi < 4; mi++) {
            int r0 = m0 + wm + mi * 16 + (lane >> 2);
#pragma unroll
            for (int ni = 0; ni < 4; ni++) {
                int cc = n0 + wn + ni * 8 + ((lane & 3) << 1);
                *(float2*)&C[(size_t)r0 * Nd + cc] =
                    make_float2(acc[mi][ni][0], acc[mi][ni][1]);
                *(float2*)&C[(size_t)(r0 + 8) * Nd + cc] =
                    make_float2(acc[mi][ni][2], acc[mi][ni][3]);
            }
        }
    } else if (MODE == 3) {
        // fp16 transposed: VT[col][row], stride 4096 (per-col 16B coalesced)
        __half* C = (__half*)Cout;
#pragma unroll
        for (int mi = 0; mi < 4; mi++) {
            int r0 = m0 + wm + mi * 16 + (lane >> 2);
#pragma unroll
            for (int ni = 0; ni < 4; ni++) {
                int cc = n0 + wn + ni * 8 + ((lane & 3) << 1);
                C[(size_t)cc * 4096 + r0] = __float2half_rn(acc[mi][ni][0]);
                C[(size_t)(cc + 1) * 4096 + r0] = __float2half_rn(acc[mi][ni][1]);
                C[(size_t)cc * 4096 + r0 + 8] = __float2half_rn(acc[mi][ni][2]);
                C[(size_t)(cc + 1) * 4096 + r0 + 8] = __float2half_rn(acc[mi][ni][3]);
            }
        }
    } else {
        // MODE 1: fused per-head RMSNorm + weight + scale, fp16 out.
        float* red = (float*)(smem + 2 * GMS);   // [256 rows][4 wn-groups]
        __syncthreads();
#pragma unroll
        for (int mi = 0; mi < 4; mi++) {
            float ss0 = 0.f, ss1 = 0.f;
#pragma unroll
            for (int ni = 0; ni < 4; ni++) {
                ss0 += acc[mi][ni][0] * acc[mi][ni][0]
                     + acc[mi][ni][1] * acc[mi][ni][1];
                ss1 += acc[mi][ni][2] * acc[mi][ni][2]
                     + acc[mi][ni][3] * acc[mi][ni][3];
            }
            ss0 += __shfl_xor_sync(0xffffffffu, ss0, 1);
            ss0 += __shfl_xor_sync(0xffffffffu, ss0, 2);
            ss1 += __shfl_xor_sync(0xffffffffu, ss1, 1);
            ss1 += __shfl_xor_sync(0xffffffffu, ss1, 2);
            if ((lane & 3) == 0) {
                int r = wm + mi * 16 + (lane >> 2);
                red[r * 4 + (wid >> 2)] = ss0;
                red[(r + 8) * 4 + (wid >> 2)] = ss1;
            }
        }
        __syncthreads();
        __half* C = (__half*)Cout;
#pragma unroll
        for (int mi = 0; mi < 4; mi++) {
            int rl = wm + mi * 16 + (lane >> 2);
            float s0 = red[rl * 4] + red[rl * 4 + 1]
                     + red[rl * 4 + 2] + red[rl * 4 + 3];
            float s1 = red[(rl + 8) * 4] + red[(rl + 8) * 4 + 1]
                     + red[(rl + 8) * 4 + 2] + red[(rl + 8) * 4 + 3];
            float inv0 = rsqrtf(s0 * (1.0f / 128.0f) + 1e-6f) * scale;
            float inv1 = rsqrtf(s1 * (1.0f / 128.0f) + 1e-6f) * scale;
            int r0 = m0 + rl;
#pragma unroll
            for (int ni = 0; ni < 4; ni++) {
                int d = wn + ni * 8 + ((lane & 3) << 1);
                float w0 = w[d], w1 = w[d + 1];
                __half2 h0 = __floats2half2_rn(acc[mi][ni][0] * inv0 * w0,
                                               acc[mi][ni][1] * inv0 * w1);
                __half2 h1 = __floats2half2_rn(acc[mi][ni][2] * inv1 * w0,
                                               acc[mi][ni][3] * inv1 * w1);
                *(uint32_t*)&C[(size_t)r0 * Nd + n0 + d] = *(uint32_t*)&h0;
                *(uint32_t*)&C[(size_t)(r0 + 8) * Nd + n0 + d] = *(uint32_t*)&h1;
            }
        }
    }
}

// ---------------------------------------------------------------------------
// Flash attention fp16 (round-14 version, unchanged): 256 queries x one head
// per CTA, 512 threads / 16 warps. K tiles of 64 keys, 2-stage cp.async.
// ---------------------------------------------------------------------------
#define FM_QH    0
#define FM_STG0  65536
#define FM_STAGE 32768
#define FM_SMEM  (65536 + 2 * FM_STAGE)   // 131072

__device__ __forceinline__ uint32_t sw256(int row, int kb) {
    return (uint32_t)(row * 256 + ((kb & 0x80) | ((kb ^ ((row & 7) << 4)) & 0x70)));
}

__global__ void __launch_bounds__(512, 1) flash_mma(
    const __half* __restrict__ Qh, const __half* __restrict__ Kh,
    const __half* __restrict__ VTh, __half* __restrict__ Oh) {
    extern __shared__ char smem[];
    const uint32_t sb = smem_u32(smem);
    const int tid = threadIdx.x;
    const int lane = tid & 31;
    const int wid = tid >> 5;
    const int h = blockIdx.y;
    const int m0 = blockIdx.x << 8;
    const int hoff = h << 7;
    const int qbase = wid << 4;

    {
        int row = tid >> 1;
        int c0 = (tid & 1) << 3;
        const __half* qh = Qh + (size_t)(m0 + row) * 2048 + hoff;
#pragma unroll
        for (int j = 0; j < 8; j++) {
            int c = c0 + j;
            CP_ASYNC16(sb + FM_QH + sw256(row, c << 4), qh + c * 8);
        }
    }

    const int krow = tid >> 3;
    const int kc0 = (tid & 7) << 1;
    const int vrow = tid >> 2;
    const int vc0 = (tid & 3) << 1;

#define FM_ISSUE(kt, buf) do {                                                  \
    uint32_t _st = sb + FM_STG0 + (buf) * FM_STAGE;                             \
    const __half* _kh = Kh + (size_t)((kt) + krow) * 2048 + hoff;               \
    _Pragma("unroll")                                                           \
    for (int _j = 0; _j < 2; _j++) {                                            \
        int _c = kc0 + _j;                                                      \
        CP_ASYNC16(_st + sw256(krow, _c << 4), _kh + _c * 8);                   \
    }                                                                           \
    const __half* _vh = VTh + (size_t)(hoff + vrow) * 4096 + (kt);              \
    _Pragma("unroll")                                                           \
    for (int _j = 0; _j < 2; _j++) {                                            \
        int _c = vc0 + _j;                                                      \
        uint32_t _sw = (uint32_t)(vrow * 128 + ((_c << 4) ^ ((vrow & 7) << 4)));\
        CP_ASYNC16(_st + 16384 + _sw, _vh + _c * 8);                            \
    }                                                                           \
} while (0)

    FM_ISSUE(0, 0);
    CP_COMMIT();

    float m0s = -1e30f, m1s = -1e30f, l0 = 0.f, l1 = 0.f;
    float o[16][4];
#pragma unroll
    for (int j = 0; j < 16; j++)
#pragma unroll
        for (int q = 0; q < 4; q++) o[j][q] = 0.f;

    const int NITER = 4096 / 64;
    for (int it = 0; it < NITER; it++) {
        const int buf = it & 1;
        CP_WAIT0();
        __syncthreads();
        if (it + 1 < NITER) {
            FM_ISSUE((it + 1) << 6, buf ^ 1);
            CP_COMMIT();
        }

        const uint32_t sKh = sb + FM_STG0 + buf * FM_STAGE;
        const uint32_t sVh = sKh + 16384;

        float s[8][4];
#pragma unroll
        for (int j = 0; j < 8; j++)
#pragma unroll
            for (int q = 0; q < 4; q++) s[j][q] = 0.f;

#pragma unroll
        for (int ks = 0; ks < 8; ks++) {
            uint32_t ah[4];
            {
                int row = qbase + (lane & 15);
                int kb = ks * 32 + ((lane >> 4) << 4);
                LDSM_X4(ah, sb + FM_QH + sw256(row, kb));
            }
#pragma unroll
            for (int pr = 0; pr < 4; pr++) {
                uint32_t bh[4];
                int row = pr * 16 + (lane & 7) + (((lane >> 4) & 1) << 3);
                int kb = ks * 32 + (((lane >> 3) & 1) << 4);
                LDSM_X4(bh, sKh + sw256(row, kb));
                MMAF16(s[2 * pr],     ah, bh[0], bh[1]);
                MMAF16(s[2 * pr + 1], ah, bh[2], bh[3]);
            }
        }

        float mx0 = -1e30f, mx1 = -1e30f;
#pragma unroll
        for (int j = 0; j < 8; j++) {
            mx0 = fmaxf(mx0, fmaxf(s[j][0], s[j][1]));
            mx1 = fmaxf(mx1, fmaxf(s[j][2], s[j][3]));
        }
        mx0 = fmaxf(mx0, __shfl_xor_sync(0xffffffffu, mx0, 1));
        mx0 = fmaxf(mx0, __shfl_xor_sync(0xffffffffu, mx0, 2));
        mx1 = fmaxf(mx1, __shfl_xor_sync(0xffffffffu, mx1, 1));
        mx1 = fmaxf(mx1, __shfl_xor_sync(0xffffffffu, mx1, 2));
        float mn0 = fmaxf(m0s, mx0), mn1 = fmaxf(m1s, mx1);
        float corr0 = ex2(m0s - mn0), corr1 = ex2(m1s - mn1);
        m0s = mn0; m1s = mn1;

        float sum0 = 0.f, sum1 = 0.f;
#pragma unroll
        for (int j = 0; j < 8; j++) {
            s[j][0] = ex2(s[j][0] - mn0);
            s[j][1] = ex2(s[j][1] - mn0);
            s[j][2] = ex2(s[j][2] - mn1);
            s[j][3] = ex2(s[j][3] - mn1);
            sum0 += s[j][0] + s[j][1];
            sum1 += s[j][2] + s[j][3];
        }
        sum0 += __shfl_xor_sync(0xffffffffu, sum0, 1);
        sum0 += __shfl_xor_sync(0xffffffffu, sum0, 2);
        sum1 += __shfl_xor_sync(0xffffffffu, sum1, 1);
        sum1 += __shfl_xor_sync(0xffffffffu, sum1, 2);
        l0 = l0 * corr0 + sum0;
        l1 = l1 * corr1 + sum1;

#pragma unroll
        for (int j = 0; j < 16; j++) {
            o[j][0] *= corr0; o[j][1] *= corr0;
            o[j][2] *= corr1; o[j][3] *= corr1;
        }

#pragma unroll
        for (int kt = 0; kt < 4; kt++) {
            uint32_t pa[4];
#pragma unroll
            for (int t = 0; t < 2; t++) {
                int j = 2 * kt + t;
#pragma unroll
                for (int half = 0; half < 2; half++) {
                    __half2 hh = __floats2half2_rn(s[j][half * 2],
                                                   s[j][half * 2 + 1]);
                    pa[t * 2 + half] = *(uint32_t*)&hh;
                }
            }
#pragma unroll
            for (int prp = 0; prp < 4; prp++) {
                uint32_t bvh[2][4];
#pragma unroll
                for (int e = 0; e < 2; e++) {
                    int pr = prp * 2 + e;
                    int row = pr * 16 + (lane & 7) + (((lane >> 4) & 1) << 3);
                    int kb = kt * 32 + (((lane >> 3) & 1) << 4);
                    uint32_t sw = (uint32_t)(row * 128 + (kb ^ ((row & 7) << 4)));
                    LDSM_X4(bvh[e], sVh + sw);
                }
#pragma unroll
                for (int q = 0; q < 4; q++)
                    MMAF16(o[prp * 4 + q], pa,
                           bvh[q >> 1][(q & 1) << 1],
                           bvh[q >> 1][((q & 1) << 1) + 1]);
            }
        }
    }

    float inv0 = 1.0f / l0, inv1 = 1.0f / l1;
    int r0 = m0 + qbase + (lane >> 2);
#pragma unroll
    for (int j = 0; j < 16; j++) {
        int prp = j >> 2, e = (j >> 1) & 1, t = j & 1;
        int ntile = (prp * 2 + e) * 2 + t;
        int cc = hoff + ntile * 8 + ((lane & 3) << 1);
        {
            __half2 hh = __floats2half2_rn(o[j][0] * inv0, o[j][1] * inv0);
            *(uint32_t*)&Oh[(size_t)r0 * 2048 + cc] = *(uint32_t*)&hh;
        }
        {
            __half2 hh = __floats2half2_rn(o[j][2] * inv1, o[j][3] * inv1);
            *(uint32_t*)&Oh[(size_t)(r0 + 8) * 2048 + cc] = *(uint32_t*)&hh;
        }
    }
}

// ---------------------------------------------------------------------------
// Launch
// ---------------------------------------------------------------------------
extern "C" void kernel_launch(void* const* d_in, const int* in_sizes, int n_in,
                              void* d_out, int out_size) {
    const float* x  = (const float*)d_in[0];
    const float* wq = (const float*)d_in[1];
    const float* wk = (const float*)d_in[2];
    const float* wv = (const float*)d_in[3];
    const float* wo = (const float*)d_in[4];
    const float* qn = (const float*)d_in[5];
    const float* kn = (const float*)d_in[6];
    float* out = (float*)d_out;

    void *pxh, *pw4, *pqh, *pkh, *pvt;
    cudaGetSymbolAddress(&pxh, g_Xh);
    cudaGetSymbolAddress(&pw4, g_W4);
    cudaGetSymbolAddress(&pqh, g_Qh);
    cudaGetSymbolAddress(&pkh, g_Kh);
    cudaGetSymbolAddress(&pvt, g_VTh);
    __half* Xh = (__half*)pxh;
    __half* W4 = (__half*)pw4;

    cudaFuncSetAttribute(gemm_mma<0>, cudaFuncAttributeMaxDynamicSharedMemorySize, GM_SMEM);
    cudaFuncSetAttribute(gemm_mma<1>, cudaFuncAttributeMaxDynamicSharedMemorySize, GM_SMEM);
    cudaFuncSetAttribute(gemm_mma<3>, cudaFuncAttributeMaxDynamicSharedMemorySize, GM_SMEM);
    cudaFuncSetAttribute(flash_mma, cudaFuncAttributeMaxDynamicSharedMemorySize, FM_SMEM);

    const int M = 4096, D = 2048;
    const int nX4 = M * D / 4;
    dim3 gg(D / 128, M / 256);      // (16, 16)

    const float qscale = 0.08838834764831845f * 1.4426950408889634f;
    const size_t WSEG = (size_t)D * D;   // 4 M fp16 elements per weight

    conv_h<<<(nX4 + 255) / 256, 256>>>(x, Xh, nX4);
    conv_w4<<<16384, 256>>>(wq, wk, wv, wo, W4);

    gemm_mma<1><<<gg, 512, GM_SMEM>>>(Xh, W4, qn, qscale, pqh);
    gemm_mma<1><<<gg, 512, GM_SMEM>>>(Xh, W4 + WSEG, kn, 1.0f, pkh);
    gemm_mma<3><<<gg, 512, GM_SMEM>>>(Xh, W4 + 2 * WSEG, nullptr, 1.0f, pvt);

    // flash writes fp16 O into Xh (A operand of O-proj); 256 queries/CTA
    flash_mma<<<dim3(M / 256, 16), 512, FM_SMEM>>>(
        (__half*)pqh, (__half*)pkh, (__half*)pvt, Xh);

    gemm_mma<0><<<gg, 512, GM_SMEM>>>(Xh, W4 + 3 * WSEG, nullptr, 1.0f, out);
}

// round 17
// speedup vs baseline: 1.3079x; 1.0125x over previous
#include <cuda_runtime.h>
#include <cuda_fp16.h>
#include <cstdint>
#include <math.h>

// ---------------- scratch (static device globals; no allocation) ----------
__device__ __half g_Xh[4096 * 2048];        // x fp16; later attention-out fp16
__device__ __half g_W4[4 * 2048 * 2048];    // wq|wk|wv|wo fp16
__device__ __half g_Qh[4096 * 2048];
__device__ __half g_Kh[4096 * 2048];
__device__ __half g_VTh[2048 * 4096];       // [h*128+d][s], fp16

// ======================= portable PTX helpers (sm_80+) =====================
__device__ __forceinline__ uint32_t smem_u32(const void* p) {
    uint32_t a;
    asm("{ .reg .u64 t; cvta.to.shared.u64 t, %1; cvt.u32.u64 %0, t; }"
        : "=r"(a) : "l"(p));
    return a;
}
#define CP_ASYNC16(dst, src) \
    asm volatile("cp.async.cg.shared.global [%0], [%1], 16;" \
                 :: "r"(dst), "l"(src))
#define CP_COMMIT() asm volatile("cp.async.commit_group;")
#define CP_WAIT1()  asm volatile("cp.async.wait_group 1;")
#define CP_WAIT0()  asm volatile("cp.async.wait_group 0;")
#define LDSM_X4(r, addr) \
    asm volatile("ldmatrix.sync.aligned.m8n8.x4.shared.b16 {%0,%1,%2,%3}, [%4];" \
                 : "=r"((r)[0]), "=r"((r)[1]), "=r"((r)[2]), "=r"((r)[3]) \
                 : "r"(addr))
#define MMAF16(d, a, b0, b1) \
    asm volatile("mma.sync.aligned.m16n8k16.row.col.f32.f16.f16.f32 " \
                 "{%0,%1,%2,%3}, {%4,%5,%6,%7}, {%8,%9}, {%0,%1,%2,%3};" \
                 : "+f"((d)[0]), "+f"((d)[1]), "+f"((d)[2]), "+f"((d)[3]) \
                 : "r"((a)[0]), "r"((a)[1]), "r"((a)[2]), "r"((a)[3]), \
                   "r"(b0), "r"(b1))
__device__ __forceinline__ float ex2(float x) {
    float r;
    asm("ex2.approx.f32 %0, %1;" : "=f"(r) : "f"(x));
    return r;
}

// ---------------------------------------------------------------------------
// convert fp32 -> fp16 (x)
// ---------------------------------------------------------------------------
__global__ void __launch_bounds__(256) conv_h(const float* __restrict__ in,
                                              __half* __restrict__ out, int n4) {
    int i = blockIdx.x * blockDim.x + threadIdx.x;
    if (i >= n4) return;
    float4 v = ((const float4*)in)[i];
    union { __half b[4]; uint2 u; } H;
    H.b[0] = __float2half_rn(v.x);
    H.b[1] = __float2half_rn(v.y);
    H.b[2] = __float2half_rn(v.z);
    H.b[3] = __float2half_rn(v.w);
    ((uint2*)out)[i] = H.u;
}

// ---------------------------------------------------------------------------
// convert all 4 weights fp32 -> fp16 into one buffer (1 launch)
// ---------------------------------------------------------------------------
__global__ void __launch_bounds__(256) conv_w4(
    const float* __restrict__ w0, const float* __restrict__ w1,
    const float* __restrict__ w2, const float* __restrict__ w3,
    __half* __restrict__ out) {
    int i = blockIdx.x * blockDim.x + threadIdx.x;
    int seg = i >> 20;
    int loc = i & 0xFFFFF;
    const float* src = (seg == 0) ? w0 : (seg == 1) ? w1 : (seg == 2) ? w2 : w3;
    float4 v = ((const float4*)src)[loc];
    union { __half b[4]; uint2 u; } H;
    H.b[0] = __float2half_rn(v.x);
    H.b[1] = __float2half_rn(v.y);
    H.b[2] = __float2half_rn(v.z);
    H.b[3] = __float2half_rn(v.w);
    ((uint2*)out)[i] = H.u;
}

// ---------------------------------------------------------------------------
// gemm fp16, CTA 256x128, 512 threads / 16 warps (warp 64x32), K chunk 64
// (128B rows, SW128 swizzle), 3-STAGE cp.async (issue 2 ahead, wait_group 1),
// 1 sync/iter, NITER=32. Epilogues: MODE 0 fp32; MODE 1 fused RMSNorm fp16;
// MODE 3 fp16 transposed (VT).
// ---------------------------------------------------------------------------
#define GMS      49152              // stage: A(32KB) + B(16KB)
#define GM_SMEM  (3 * GMS + 4096)   // 151552

template <int MODE>
__global__ void __launch_bounds__(512, 1) gemm_mma(
    const __half* __restrict__ Ah, const __half* __restrict__ Bh,
    const float* __restrict__ w, float scale, void* __restrict__ Cout) {
    constexpr int Nd = 2048, Kd = 2048;
    extern __shared__ char smem[];
    const uint32_t sbase = smem_u32(smem);
    const int tid = threadIdx.x;
    const int lane = tid & 31;
    const int wid = tid >> 5;
    const int m0 = blockIdx.y << 8;
    const int n0 = blockIdx.x << 7;
    const int wm = (wid & 3) << 6;
    const int wn = (wid >> 2) << 5;

    float acc[4][4][4];
#pragma unroll
    for (int mi = 0; mi < 4; mi++)
#pragma unroll
        for (int ni = 0; ni < 4; ni++)
#pragma unroll
            for (int q = 0; q < 4; q++) acc[mi][ni][q] = 0.f;

    const int arow = tid >> 1;
    const int ac0 = (tid & 1) << 2;
    const int brow = tid >> 2;
    const int bc0 = (tid & 3) << 1;

    auto issue = [&](int it, int stage) {
        int kk = it << 6;
        const __half* pA = Ah + (size_t)(m0 + arow) * Kd + kk;
        uint32_t stA = sbase + stage * GMS + arow * 128;
#pragma unroll
        for (int j = 0; j < 4; j++) {
            int c = ac0 + j;
            CP_ASYNC16(stA + ((uint32_t)(c ^ (arow & 7)) << 4), pA + c * 8);
        }
        const __half* pB = Bh + (size_t)(n0 + brow) * Kd + kk;
        uint32_t stB = sbase + stage * GMS + 32768 + brow * 128;
#pragma unroll
        for (int j = 0; j < 2; j++) {
            int c = bc0 + j;
            CP_ASYNC16(stB + ((uint32_t)(c ^ (brow & 7)) << 4), pB + c * 8);
        }
    };

    issue(0, 0); CP_COMMIT();
    issue(1, 1); CP_COMMIT();

    constexpr int NITER = 32;
    int stage = 0, nstage = 2;
    for (int it = 0; it < NITER; it++) {
        if (it < NITER - 1) CP_WAIT1(); else CP_WAIT0();
        __syncthreads();
        if (it + 2 < NITER) { issue(it + 2, nstage); CP_COMMIT(); }

        const uint32_t sA = sbase + stage * GMS;
        const uint32_t sB = sA + 32768;

#pragma unroll
        for (int ks = 0; ks < 4; ks++) {
            uint32_t bh[2][4];
#pragma unroll
            for (int pr = 0; pr < 2; pr++) {
                int row = wn + pr * 16 + (lane & 7) + (((lane >> 4) & 1) << 3);
                int c = ks * 2 + ((lane >> 3) & 1);
                uint32_t off = (uint32_t)(row * 128 + ((c ^ (row & 7)) << 4));
                LDSM_X4(bh[pr], sB + off);
            }
#pragma unroll
            for (int mi = 0; mi < 4; mi++) {
                uint32_t ah[4];
                int row = wm + mi * 16 + (lane & 15);
                int c = ks * 2 + (lane >> 4);
                uint32_t off = (uint32_t)(row * 128 + ((c ^ (row & 7)) << 4));
                LDSM_X4(ah, sA + off);
#pragma unroll
                for (int ni = 0; ni < 4; ni++)
                    MMAF16(acc[mi][ni], ah,
                           bh[ni >> 1][(ni & 1) << 1],
                           bh[ni >> 1][((ni & 1) << 1) + 1]);
            }
        }
        stage = (stage == 2) ? 0 : stage + 1;
        nstage = (nstage == 2) ? 0 : nstage + 1;
    }

    if (MODE == 0) {
        float* C = (float*)Cout;
#pragma unroll
        for (int mi = 0; mi < 4; mi++) {
            int r0 = m0 + wm + mi * 16 + (lane >> 2);
#pragma unroll
            for (int ni = 0; ni < 4; ni++) {
                int cc = n0 + wn + ni * 8 + ((lane & 3) << 1);
                *(float2*)&C[(size_t)r0 * Nd + cc] =
                    make_float2(acc[mi][ni][0], acc[mi][ni][1]);
                *(float2*)&C[(size_t)(r0 + 8) * Nd + cc] =
                    make_float2(acc[mi][ni][2], acc[mi][ni][3]);
            }
        }
    } else if (MODE == 3) {
        __half* C = (__half*)Cout;
#pragma unroll
        for (int mi = 0; mi < 4; mi++) {
            int r0 = m0 + wm + mi * 16 + (lane >> 2);
#pragma unroll
            for (int ni = 0; ni < 4; ni++) {
                int cc = n0 + wn + ni * 8 + ((lane & 3) << 1);
                C[(size_t)cc * 4096 + r0] = __float2half_rn(acc[mi][ni][0]);
                C[(size_t)(cc + 1) * 4096 + r0] = __float2half_rn(acc[mi][ni][1]);
                C[(size_t)cc * 4096 + r0 + 8] = __float2half_rn(acc[mi][ni][2]);
                C[(size_t)(cc + 1) * 4096 + r0 + 8] = __float2half_rn(acc[mi][ni][3]);
            }
        }
    } else {
        float* red = (float*)(smem + 3 * GMS);
        __syncthreads();
#pragma unroll
        for (int mi = 0; mi < 4; mi++) {
            float ss0 = 0.f, ss1 = 0.f;
#pragma unroll
            for (int ni = 0; ni < 4; ni++) {
                ss0 += acc[mi][ni][0] * acc[mi][ni][0]
                     + acc[mi][ni][1] * acc[mi][ni][1];
                ss1 += acc[mi][ni][2] * acc[mi][ni][2]
                     + acc[mi][ni][3] * acc[mi][ni][3];
            }
            ss0 += __shfl_xor_sync(0xffffffffu, ss0, 1);
            ss0 += __shfl_xor_sync(0xffffffffu, ss0, 2);
            ss1 += __shfl_xor_sync(0xffffffffu, ss1, 1);
            ss1 += __shfl_xor_sync(0xffffffffu, ss1, 2);
            if ((lane & 3) == 0) {
                int r = wm + mi * 16 + (lane >> 2);
                red[r * 4 + (wid >> 2)] = ss0;
                red[(r + 8) * 4 + (wid >> 2)] = ss1;
            }
        }
        __syncthreads();
        __half* C = (__half*)Cout;
#pragma unroll
        for (int mi = 0; mi < 4; mi++) {
            int rl = wm + mi * 16 + (lane >> 2);
            float s0 = red[rl * 4] + red[rl * 4 + 1]
                     + red[rl * 4 + 2] + red[rl * 4 + 3];
            float s1 = red[(rl + 8) * 4] + red[(rl + 8) * 4 + 1]
                     + red[(rl + 8) * 4 + 2] + red[(rl + 8) * 4 + 3];
            float inv0 = rsqrtf(s0 * (1.0f / 128.0f) + 1e-6f) * scale;
            float inv1 = rsqrtf(s1 * (1.0f / 128.0f) + 1e-6f) * scale;
            int r0 = m0 + rl;
#pragma unroll
            for (int ni = 0; ni < 4; ni++) {
                int d = wn + ni * 8 + ((lane & 3) << 1);
                float w0 = w[d], w1 = w[d + 1];
                __half2 h0 = __floats2half2_rn(acc[mi][ni][0] * inv0 * w0,
                                               acc[mi][ni][1] * inv0 * w1);
                __half2 h1 = __floats2half2_rn(acc[mi][ni][2] * inv1 * w0,
                                               acc[mi][ni][3] * inv1 * w1);
                *(uint32_t*)&C[(size_t)r0 * Nd + n0 + d] = *(uint32_t*)&h0;
                *(uint32_t*)&C[(size_t)(r0 + 8) * Nd + n0 + d] = *(uint32_t*)&h1;
            }
        }
    }
}

// ---------------------------------------------------------------------------
// Flash attention fp16: 256 queries x one head per CTA, 512 threads /
// 16 warps. K tiles of 64 keys, 3-STAGE cp.async (issue 2 ahead, wait 1).
// ---------------------------------------------------------------------------
#define FM_QH    0
#define FM_STG0  65536
#define FM_STAGE 32768
#define FM_SMEM  (65536 + 3 * FM_STAGE)   // 163840

__device__ __forceinline__ uint32_t sw256(int row, int kb) {
    return (uint32_t)(row * 256 + ((kb & 0x80) | ((kb ^ ((row & 7) << 4)) & 0x70)));
}

__global__ void __launch_bounds__(512, 1) flash_mma(
    const __half* __restrict__ Qh, const __half* __restrict__ Kh,
    const __half* __restrict__ VTh, __half* __restrict__ Oh) {
    extern __shared__ char smem[];
    const uint32_t sb = smem_u32(smem);
    const int tid = threadIdx.x;
    const int lane = tid & 31;
    const int wid = tid >> 5;
    const int h = blockIdx.y;
    const int m0 = blockIdx.x << 8;
    const int hoff = h << 7;
    const int qbase = wid << 4;

    {
        int row = tid >> 1;
        int c0 = (tid & 1) << 3;
        const __half* qh = Qh + (size_t)(m0 + row) * 2048 + hoff;
#pragma unroll
        for (int j = 0; j < 8; j++) {
            int c = c0 + j;
            CP_ASYNC16(sb + FM_QH + sw256(row, c << 4), qh + c * 8);
        }
    }

    const int krow = tid >> 3;
    const int kc0 = (tid & 7) << 1;
    const int vrow = tid >> 2;
    const int vc0 = (tid & 3) << 1;

#define FM_ISSUE(kt, buf) do {                                                  \
    uint32_t _st = sb + FM_STG0 + (buf) * FM_STAGE;                             \
    const __half* _kh = Kh + (size_t)((kt) + krow) * 2048 + hoff;               \
    _Pragma("unroll")                                                           \
    for (int _j = 0; _j < 2; _j++) {                                            \
        int _c = kc0 + _j;                                                      \
        CP_ASYNC16(_st + sw256(krow, _c << 4), _kh + _c * 8);                   \
    }                                                                           \
    const __half* _vh = VTh + (size_t)(hoff + vrow) * 4096 + (kt);              \
    _Pragma("unroll")                                                           \
    for (int _j = 0; _j < 2; _j++) {                                            \
        int _c = vc0 + _j;                                                      \
        uint32_t _sw = (uint32_t)(vrow * 128 + ((_c << 4) ^ ((vrow & 7) << 4)));\
        CP_ASYNC16(_st + 16384 + _sw, _vh + _c * 8);                            \
    }                                                                           \
} while (0)

    FM_ISSUE(0, 0);
    CP_COMMIT();
    FM_ISSUE(64, 1);
    CP_COMMIT();

    float m0s = -1e30f, m1s = -1e30f, l0 = 0.f, l1 = 0.f;
    float o[16][4];
#pragma unroll
    for (int j = 0; j < 16; j++)
#pragma unroll
        for (int q = 0; q < 4; q++) o[j][q] = 0.f;

    const int NITER = 4096 / 64;
    int buf = 0, nbuf = 2;
    for (int it = 0; it < NITER; it++) {
        if (it < NITER - 1) CP_WAIT1(); else CP_WAIT0();
        __syncthreads();
        if (it + 2 < NITER) {
            FM_ISSUE((it + 2) << 6, nbuf);
            CP_COMMIT();
        }

        const uint32_t sKh = sb + FM_STG0 + buf * FM_STAGE;
        const uint32_t sVh = sKh + 16384;

        float s[8][4];
#pragma unroll
        for (int j = 0; j < 8; j++)
#pragma unroll
            for (int q = 0; q < 4; q++) s[j][q] = 0.f;

#pragma unroll
        for (int ks = 0; ks < 8; ks++) {
            uint32_t ah[4];
            {
                int row = qbase + (lane & 15);
                int kb = ks * 32 + ((lane >> 4) << 4);
                LDSM_X4(ah, sb + FM_QH + sw256(row, kb));
            }
#pragma unroll
            for (int pr = 0; pr < 4; pr++) {
                uint32_t bh[4];
                int row = pr * 16 + (lane & 7) + (((lane >> 4) & 1) << 3);
                int kb = ks * 32 + (((lane >> 3) & 1) << 4);
                LDSM_X4(bh, sKh + sw256(row, kb));
                MMAF16(s[2 * pr],     ah, bh[0], bh[1]);
                MMAF16(s[2 * pr + 1], ah, bh[2], bh[3]);
            }
        }

        float mx0 = -1e30f, mx1 = -1e30f;
#pragma unroll
        for (int j = 0; j < 8; j++) {
            mx0 = fmaxf(mx0, fmaxf(s[j][0], s[j][1]));
            mx1 = fmaxf(mx1, fmaxf(s[j][2], s[j][3]));
        }
        mx0 = fmaxf(mx0, __shfl_xor_sync(0xffffffffu, mx0, 1));
        mx0 = fmaxf(mx0, __shfl_xor_sync(0xffffffffu, mx0, 2));
        mx1 = fmaxf(mx1, __shfl_xor_sync(0xffffffffu, mx1, 1));
        mx1 = fmaxf(mx1, __shfl_xor_sync(0xffffffffu, mx1, 2));
        float mn0 = fmaxf(m0s, mx0), mn1 = fmaxf(m1s, mx1);
        float corr0 = ex2(m0s - mn0), corr1 = ex2(m1s - mn1);
        m0s = mn0; m1s = mn1;

        float sum0 = 0.f, sum1 = 0.f;
#pragma unroll
        for (int j = 0; j < 8; j++) {
            s[j][0] = ex2(s[j][0] - mn0);
            s[j][1] = ex2(s[j][1] - mn0);
            s[j][2] = ex2(s[j][2] - mn1);
            s[j][3] = ex2(s[j][3] - mn1);
            sum0 += s[j][0] + s[j][1];
            sum1 += s[j][2] + s[j][3];
        }
        sum0 += __shfl_xor_sync(0xffffffffu, sum0, 1);
        sum0 += __shfl_xor_sync(0xffffffffu, sum0, 2);
        sum1 += __shfl_xor_sync(0xffffffffu, sum1, 1);
        sum1 += __shfl_xor_sync(0xffffffffu, sum1, 2);
        l0 = l0 * corr0 + sum0;
        l1 = l1 * corr1 + sum1;

#pragma unroll
        for (int j = 0; j < 16; j++) {
            o[j][0] *= corr0; o[j][1] *= corr0;
            o[j][2] *= corr1; o[j][3] *= corr1;
        }

#pragma unroll
        for (int kt = 0; kt < 4; kt++) {
            uint32_t pa[4];
#pragma unroll
            for (int t = 0; t < 2; t++) {
                int j = 2 * kt + t;
#pragma unroll
                for (int half = 0; half < 2; half++) {
                    __half2 hh = __floats2half2_rn(s[j][half * 2],
                                                   s[j][half * 2 + 1]);
                    pa[t * 2 + half] = *(uint32_t*)&hh;
                }
            }
#pragma unroll
            for (int prp = 0; prp < 4; prp++) {
                uint32_t bvh[2][4];
#pragma unroll
                for (int e = 0; e < 2; e++) {
                    int pr = prp * 2 + e;
                    int row = pr * 16 + (lane & 7) + (((lane >> 4) & 1) << 3);
                    int kb = kt * 32 + (((lane >> 3) & 1) << 4);
                    uint32_t sw = (uint32_t)(row * 128 + (kb ^ ((row & 7) << 4)));
                    LDSM_X4(bvh[e], sVh + sw);
                }
#pragma unroll
                for (int q = 0; q < 4; q++)
                    MMAF16(o[prp * 4 + q], pa,
                           bvh[q >> 1][(q & 1) << 1],
                           bvh[q >> 1][((q & 1) << 1) + 1]);
            }
        }
        buf = (buf == 2) ? 0 : buf + 1;
        nbuf = (nbuf == 2) ? 0 : nbuf + 1;
    }

    float inv0 = 1.0f / l0, inv1 = 1.0f / l1;
    int r0 = m0 + qbase + (lane >> 2);
#pragma unroll
    for (int j = 0; j < 16; j++) {
        int prp = j >> 2, e = (j >> 1) & 1, t = j & 1;
        int ntile = (prp * 2 + e) * 2 + t;
        int cc = hoff + ntile * 8 + ((lane & 3) << 1);
        {
            __half2 hh = __floats2half2_rn(o[j][0] * inv0, o[j][1] * inv0);
            *(uint32_t*)&Oh[(size_t)r0 * 2048 + cc] = *(uint32_t*)&hh;
        }
        {
            __half2 hh = __floats2half2_rn(o[j][2] * inv1, o[j][3] * inv1);
            *(uint32_t*)&Oh[(size_t)(r0 + 8) * 2048 + cc] = *(uint32_t*)&hh;
        }
    }
}

// ---------------------------------------------------------------------------
// Launch
// ---------------------------------------------------------------------------
extern "C" void kernel_launch(void* const* d_in, const int* in_sizes, int n_in,
                              void* d_out, int out_size) {
    const float* x  = (const float*)d_in[0];
    const float* wq = (const float*)d_in[1];
    const float* wk = (const float*)d_in[2];
    const float* wv = (const float*)d_in[3];
    const float* wo = (const float*)d_in[4];
    const float* qn = (const float*)d_in[5];
    const float* kn = (const float*)d_in[6];
    float* out = (float*)d_out;

    void *pxh, *pw4, *pqh, *pkh, *pvt;
    cudaGetSymbolAddress(&pxh, g_Xh);
    cudaGetSymbolAddress(&pw4, g_W4);
    cudaGetSymbolAddress(&pqh, g_Qh);
    cudaGetSymbolAddress(&pkh, g_Kh);
    cudaGetSymbolAddress(&pvt, g_VTh);
    __half* Xh = (__half*)pxh;
    __half* W4 = (__half*)pw4;

    cudaFuncSetAttribute(gemm_mma<0>, cudaFuncAttributeMaxDynamicSharedMemorySize, GM_SMEM);
    cudaFuncSetAttribute(gemm_mma<1>, cudaFuncAttributeMaxDynamicSharedMemorySize, GM_SMEM);
    cudaFuncSetAttribute(gemm_mma<3>, cudaFuncAttributeMaxDynamicSharedMemorySize, GM_SMEM);
    cudaFuncSetAttribute(flash_mma, cudaFuncAttributeMaxDynamicSharedMemorySize, FM_SMEM);

    const int M = 4096, D = 2048;
    const int nX4 = M * D / 4;
    dim3 gg(D / 128, M / 256);      // (16, 16)

    const float qscale = 0.08838834764831845f * 1.4426950408889634f;
    const size_t WSEG = (size_t)D * D;

    conv_h<<<(nX4 + 255) / 256, 256>>>(x, Xh, nX4);
    conv_w4<<<16384, 256>>>(wq, wk, wv, wo, W4);

    gemm_mma<1><<<gg, 512, GM_SMEM>>>(Xh, W4, qn, qscale, pqh);
    gemm_mma<1><<<gg, 512, GM_SMEM>>>(Xh, W4 + WSEG, kn, 1.0f, pkh);
    gemm_mma<3><<<gg, 512, GM_SMEM>>>(Xh, W4 + 2 * WSEG, nullptr, 1.0f, pvt);

    flash_mma<<<dim3(M / 256, 16), 512, FM_SMEM>>>(
        (__half*)pqh, (__half*)pkh, (__half*)pvt, Xh);

    gemm_mma<0><<<gg, 512, GM_SMEM>>>(Xh, W4 + 3 * WSEG, nullptr, 1.0f, out);
}